// round 13
// baseline (speedup 1.0000x reference)
#include <cuda_runtime.h>
#include <cuda_bf16.h>
#include <stdint.h>

#define GN 4096
#define GH 8
#define FCAT 512
#define HIDF 64
#define ADJW (GN/32)
#define JS1 4
#define JS2 16
#define LOG2E 1.4426950408889634f

// ---------------- scratch ----------------
__device__ uint32_t      g_adjbits[GN * ADJW];
__device__ __nv_bfloat16 g_xb[GN * FCAT];
__device__ __nv_bfloat16 g_Wb[FCAT * FCAT];
__device__ __nv_bfloat16 g_W2b[HIDF * FCAT];
__device__ float         g_wh1[GN * FCAT];
__device__ __nv_bfloat16 g_whTb[FCAT * GN];
__device__ float         g_s1[GH * GN];
__device__ float         g_s2[GH * GN];
__device__ float         g_e2[GH * GN];     // ex2(s2)
__device__ float         g_e2b[GH * GN];    // ex2(0.2*s2)
__device__ unsigned      g_gmaxi[16];
__device__ __nv_bfloat16 g_hbufb[GN * FCAT];
__device__ float         g_wh2[GN * HIDF];
__device__ __nv_bfloat16 g_whT2b[HIDF * GN];
__device__ float         g_s21[GN];
__device__ float         g_s22[GN];
__device__ float         g_e22[GN];
__device__ float         g_e22b[GN];
__device__ float         g_part[32 * GN * 72];    // 32 slots x [row][72]

__device__ __forceinline__ unsigned fenc(float f) {
    unsigned b = __float_as_uint(f);
    return (b & 0x80000000u) ? ~b : (b | 0x80000000u);
}
__device__ __forceinline__ float fdec(unsigned k) {
    return __uint_as_float((k & 0x80000000u) ? (k & 0x7fffffffu) : ~k);
}
__device__ __forceinline__ float ex2f(float x) {
    float y; asm("ex2.approx.f32 %0, %1;" : "=f"(y) : "f"(x)); return y;
}
__device__ __forceinline__ uint32_t sptr(const void* p) {
    return (uint32_t)__cvta_generic_to_shared(p);
}
__device__ __forceinline__ void ldsm4(uint32_t* r, uint32_t a) {
    asm volatile("ldmatrix.sync.aligned.m8n8.x4.shared.b16 {%0,%1,%2,%3}, [%4];"
                 : "=r"(r[0]), "=r"(r[1]), "=r"(r[2]), "=r"(r[3]) : "r"(a));
}
__device__ __forceinline__ void ldsm2(uint32_t* r, uint32_t a) {
    asm volatile("ldmatrix.sync.aligned.m8n8.x2.shared.b16 {%0,%1}, [%2];"
                 : "=r"(r[0]), "=r"(r[1]) : "r"(a));
}
__device__ __forceinline__ void cpa16(uint32_t dst, const void* src) {
    asm volatile("cp.async.cg.shared.global [%0], [%1], 16;" :: "r"(dst), "l"(src));
}
__device__ __forceinline__ void cpa_commit() {
    asm volatile("cp.async.commit_group;");
}
template<int N>
__device__ __forceinline__ void cpa_wait() {
    asm volatile("cp.async.wait_group %0;" :: "n"(N));
}
__device__ __forceinline__ void mma16816(float* d, const uint32_t* a,
                                         uint32_t b0, uint32_t b1) {
    asm volatile(
        "mma.sync.aligned.m16n8k16.row.col.f32.bf16.bf16.f32 "
        "{%0,%1,%2,%3}, {%4,%5,%6,%7}, {%8,%9}, {%0,%1,%2,%3};"
        : "+f"(d[0]), "+f"(d[1]), "+f"(d[2]), "+f"(d[3])
        : "r"(a[0]), "r"(a[1]), "r"(a[2]), "r"(a[3]), "r"(b0), "r"(b1));
}

// ---------------- pack adjacency (4x unrolled) + init gmax ----------------
__global__ void pack_adj_kernel(const int* __restrict__ adj,
                                uint32_t* __restrict__ bits,
                                unsigned* __restrict__ gmaxi) {
    if (blockIdx.x == 0 && threadIdx.x < 16) gmaxi[threadIdx.x] = 0u;
    int wg   = (blockIdx.x * 256 + threadIdx.x) >> 5;
    int lane = threadIdx.x & 31;
    int base = wg * 128;
    int v0 = adj[base + lane];
    int v1 = adj[base + 32 + lane];
    int v2 = adj[base + 64 + lane];
    int v3 = adj[base + 96 + lane];
    uint32_t b[4];
    b[0] = __ballot_sync(0xffffffffu, v0 > 0);
    b[1] = __ballot_sync(0xffffffffu, v1 > 0);
    b[2] = __ballot_sync(0xffffffffu, v2 > 0);
    b[3] = __ballot_sync(0xffffffffu, v3 > 0);
    if (lane < 4) bits[wg * 4 + lane] = b[lane];
}

// ---------------- fp32 -> bf16, all three inputs in one launch ------------
__global__ void cvt_all_kernel(const float* __restrict__ x, __nv_bfloat16* __restrict__ xb,
                               const float* __restrict__ W, __nv_bfloat16* __restrict__ Wb,
                               const float* __restrict__ W2, __nv_bfloat16* __restrict__ W2b) {
    const int NX = GN * FCAT / 2, NW = FCAT * FCAT / 2;
    int id = blockIdx.x * 256 + threadIdx.x;
    const float* src; __nv_bfloat16* dst; int off;
    if (id < NX)           { src = x;  dst = xb;  off = id; }
    else if (id < NX + NW) { src = W;  dst = Wb;  off = id - NX; }
    else                   { src = W2; dst = W2b; off = id - NX - NW; }
    float2 v = *(const float2*)(src + (size_t)off * 2);
    *(__nv_bfloat162*)(dst + (size_t)off * 2) = __floats2bfloat162_rn(v.x, v.y);
}

// ---------------- fp32 [GN][C] -> bf16 transposed [C][GN] ----------------
__global__ void transpose_cvt_kernel(const float* __restrict__ in,
                                     __nv_bfloat16* __restrict__ out, int C) {
    __shared__ float tile[32][33];
    int tx = threadIdx.x, ty = threadIdx.y;
    int c0 = blockIdx.x * 32;
    int r0 = blockIdx.y * 32;
#pragma unroll
    for (int k = 0; k < 4; ++k)
        tile[ty + k * 8][tx] = in[(size_t)(r0 + ty + k * 8) * C + c0 + tx];
    __syncthreads();
#pragma unroll
    for (int k = 0; k < 4; ++k)
        out[(size_t)(c0 + ty + k * 8) * GN + r0 + tx] =
            __float2bfloat16(tile[tx][ty + k * 8]);
}

// ---------------- bf16 NT GEMM, cp.async double-buffered (Kc=32) ----------
__global__ void __launch_bounds__(256, 3)
gemm_bf16_nt(const __nv_bfloat16* __restrict__ A,
             const __nv_bfloat16* __restrict__ B,
             float* __restrict__ C, int K, int Ncols) {
    __shared__ __nv_bfloat16 As[2][128 * 40];
    __shared__ __nv_bfloat16 Bs[2][64 * 40];

    const int t  = threadIdx.x;
    const int m0 = blockIdx.y * 128;
    const int n0 = blockIdx.x * 64;
    const int w = t >> 5, ln = t & 31;
    const int r = ln >> 2, c = ln & 3;

    const uint32_t aB = sptr(As[0]) + (uint32_t)(((w * 16 + (ln & 15)) * 40 +
                                                  ((ln >> 4) & 1) * 8) * 2);
    const uint32_t bB = sptr(Bs[0]) + (uint32_t)((((ln & 7) + ((ln >> 4) & 1) * 8) * 40 +
                                                  ((ln >> 3) & 1) * 8) * 2);
    const uint32_t ABUF = 128 * 40 * 2;
    const uint32_t BBUF = 64 * 40 * 2;

    float acc[8][4];
#pragma unroll
    for (int nt = 0; nt < 8; ++nt)
#pragma unroll
        for (int q = 0; q < 4; ++q) acc[nt][q] = 0.f;

    auto g_issue = [&](int ki) {
        int buf = ki & 1;
        int kc = ki * 32;
#pragma unroll
        for (int it = 0; it < 2; ++it) {
            int idx = it * 256 + t;
            int row = idx >> 2, u = idx & 3;
            cpa16(sptr(&As[buf][row * 40 + u * 8]),
                  A + (size_t)(m0 + row) * K + kc + u * 8);
        }
        {
            int row = t >> 2, u = t & 3;
            cpa16(sptr(&Bs[buf][row * 40 + u * 8]),
                  B + (size_t)(n0 + row) * K + kc + u * 8);
        }
    };

    const int NK = K / 32;
    g_issue(0); cpa_commit();
    for (int ki = 0; ki < NK; ++ki) {
        if (ki + 1 < NK) { g_issue(ki + 1); cpa_commit(); cpa_wait<1>(); }
        else             { cpa_wait<0>(); }
        __syncthreads();
        const int buf = ki & 1;
#pragma unroll
        for (int kt = 0; kt < 2; ++kt) {
            uint32_t a[4];
            ldsm4(a, aB + buf * ABUF + kt * 32);
#pragma unroll
            for (int p = 0; p < 4; ++p) {
                uint32_t b[4];
                ldsm4(b, bB + buf * BBUF + p * 1280 + kt * 32);
                mma16816(acc[2 * p],     a, b[0], b[1]);
                mma16816(acc[2 * p + 1], a, b[2], b[3]);
            }
        }
        __syncthreads();
    }
    int rA = m0 + w * 16 + r;
#pragma unroll
    for (int nt = 0; nt < 8; ++nt) {
        int col = n0 + nt * 8 + c * 2;
        *(float2*)&C[(size_t)rA * Ncols + col]       = make_float2(acc[nt][0], acc[nt][1]);
        *(float2*)&C[(size_t)(rA + 8) * Ncols + col] = make_float2(acc[nt][2], acc[nt][3]);
    }
}

// ---------------- layer-1 scores: warp per row, all 8 heads ---------------
__global__ void scores1_kernel(const float* __restrict__ wh1,
                               const float* __restrict__ a1, const float* __restrict__ a2,
                               float* __restrict__ s1, float* __restrict__ s2,
                               float* __restrict__ e2, float* __restrict__ e2b,
                               unsigned* __restrict__ gmaxi) {
    __shared__ float a1s[FCAT], a2s[FCAT];
    int t = threadIdx.x;
    for (int idx = t; idx < FCAT; idx += 256) { a1s[idx] = a1[idx]; a2s[idx] = a2[idx]; }
    __syncthreads();
    int w = t >> 5, ln = t & 31;
    int i = blockIdx.x * 8 + w;
    const float4* row = (const float4*)(wh1 + (size_t)i * FCAT);
    float p1 = 0.f, p2 = 0.f;
#pragma unroll
    for (int q = 0; q < 4; ++q) {
        float4 v  = row[ln * 4 + q];
        float4 x1 = *(const float4*)&a1s[ln * 16 + q * 4];
        float4 x2 = *(const float4*)&a2s[ln * 16 + q * 4];
        p1 += v.x * x1.x + v.y * x1.y + v.z * x1.z + v.w * x1.w;
        p2 += v.x * x2.x + v.y * x2.y + v.z * x2.z + v.w * x2.w;
    }
    p1 += __shfl_down_sync(0xffffffffu, p1, 2);
    p2 += __shfl_down_sync(0xffffffffu, p2, 2);
    p1 += __shfl_down_sync(0xffffffffu, p1, 1);
    p2 += __shfl_down_sync(0xffffffffu, p2, 1);
    if ((ln & 3) == 0) {
        int h = ln >> 2;
        p1 *= LOG2E; p2 *= LOG2E;
        s1[h * GN + i]  = p1;
        s2[h * GN + i]  = p2;
        e2[h * GN + i]  = ex2f(p2);
        e2b[h * GN + i] = ex2f(0.2f * p2);
        atomicMax(&gmaxi[h], fenc(p2));
    }
}

// ---------------- layer-2 scores (warp per (i,h)) --------------------------
__global__ void scores_kernel(const float* __restrict__ wh, int stride, int nH,
                              const float* __restrict__ a1, const float* __restrict__ a2,
                              float* __restrict__ s1, float* __restrict__ s2,
                              float* __restrict__ e2, float* __restrict__ e2b,
                              unsigned* __restrict__ gmaxi) {
    int w    = blockIdx.x * 8 + (threadIdx.x >> 5);
    int lane = threadIdx.x & 31;
    int i = w / nH, h = w % nH;
    const float* base = wh + (size_t)i * stride + h * 64;
    float v0 = base[lane], v1 = base[lane + 32];
    float p1 = v0 * a1[h * 64 + lane] + v1 * a1[h * 64 + lane + 32];
    float p2 = v0 * a2[h * 64 + lane] + v1 * a2[h * 64 + lane + 32];
#pragma unroll
    for (int o = 16; o; o >>= 1) {
        p1 += __shfl_down_sync(0xffffffffu, p1, o);
        p2 += __shfl_down_sync(0xffffffffu, p2, o);
    }
    if (lane == 0) {
        p1 *= LOG2E; p2 *= LOG2E;
        s1[h * GN + i]  = p1;
        s2[h * GN + i]  = p2;
        e2[h * GN + i]  = ex2f(p2);
        e2b[h * GN + i] = ex2f(0.2f * p2);
        atomicMax(&gmaxi[h], fenc(p2));
    }
}

// ---------------- fused masked softmax + att@wh, overlapped phases --------
// ps is WARP-LOCAL (thread t writes row t>>1; warp w's ldsm reads only rows
// [16w,16w+16)). Per tile: load all A-frags, then compute phase1(tt+1)
// (interleaved by scheduler with B-ldsm/MMA), no syncwarp needed — the
// loop-top syncthreads (for whs cp.async) provides cross-lane visibility.
// E2/E2b tables preloaded for the block's whole j-range (<=8KB smem).
template<int JS>
__global__ void __launch_bounds__(256, 3)
attn_mma_kernel(const __nv_bfloat16* __restrict__ whT,
                const float* __restrict__ s1g,
                const float* __restrict__ e2g, const float* __restrict__ e2bg,
                const unsigned* __restrict__ gmaxi,
                const uint32_t* __restrict__ adjbits,
                float* __restrict__ part) {
    constexpr int NJ = GN / JS;
    constexpr int NT = NJ / 64;
    __shared__ __nv_bfloat16 ps[128 * 72];
    __shared__ __nv_bfloat16 whs[2][72 * 72];
    __shared__ float e2s[NJ];
    __shared__ float e2bs[NJ];

    const int t  = threadIdx.x;
    const int i0 = blockIdx.x * 128;
    const int h  = blockIdx.y;
    const int jbase = blockIdx.z * NJ;

    const __nv_bfloat16* whTh = whT + (size_t)h * 64 * GN;
    uint32_t* psW = reinterpret_cast<uint32_t*>(ps);

    // constant rows 64..71 of both whs buffers (row 64 = ones -> den column)
#pragma unroll
    for (int b = 0; b < 2; ++b)
        for (int idx = t; idx < 8 * 36; idx += 256) {
            int rr = idx / 36, wd = idx - rr * 36;
            reinterpret_cast<uint32_t*>(whs[b])[(64 + rr) * 36 + wd] =
                (rr == 0) ? 0x3F803F80u : 0u;
        }

    auto issue_tile = [&](int tt) {
        int buf = tt & 1;
        int j0 = jbase + tt * 64;
#pragma unroll
        for (int it = 0; it < 2; ++it) {
            int idx = it * 256 + t;
            int f = idx >> 3, u = idx & 7;
            cpa16(sptr(&whs[buf][f * 72 + u * 8]), whTh + (size_t)f * GN + j0 + u * 8);
        }
    };

    // preload E2/E2b for whole j-range + first wh tile, one group
    {
        const float* e2h  = e2g  + h * GN + jbase;
        const float* e2bh = e2bg + h * GN + jbase;
        for (int idx = t * 4; idx < NJ; idx += 1024) {
            cpa16(sptr(&e2s[idx]),  e2h  + idx);
            cpa16(sptr(&e2bs[idx]), e2bh + idx);
        }
    }
    issue_tile(0);
    cpa_commit();

    const int rt = t >> 1, jh = t & 1;          // phase-1: row / adj-word half
    const float s1i = s1g[h * GN + i0 + rt];
    const float gme = s1i + fdec(gmaxi[h]);
    const float m   = fmaxf(gme, 0.2f * gme);
    const float ci  = ex2f(s1i - m);
    const float ci2 = ex2f(0.2f * s1i - m);

    const int w = t >> 5, ln = t & 31;
    const int r = ln >> 2, c = ln & 3;

    const uint32_t psB = sptr(ps) + (uint32_t)(((w * 16 + (ln & 15)) * 72 +
                                                ((ln >> 4) & 1) * 8) * 2);
    const uint32_t whB0 = sptr(whs[0]) + (uint32_t)((((ln & 7) + ((ln >> 4) & 1) * 8) * 72 +
                                                     ((ln >> 3) & 1) * 8) * 2);
    const uint32_t dnB0 = sptr(whs[0]) + (uint32_t)(((64 + (ln & 7)) * 72 +
                                                     ((ln >> 3) & 1) * 8) * 2);
    const uint32_t bufStride = (uint32_t)(72 * 72 * 2);

    const uint32_t* adjRow = adjbits + (size_t)(i0 + rt) * ADJW;

    auto phase1 = [&](int tt) {
        const uint32_t wv = adjRow[((jbase + tt * 64) >> 5) + jh];
        const float2* e2p  = reinterpret_cast<const float2*>(e2s  + tt * 64 + jh * 32);
        const float2* e2bp = reinterpret_cast<const float2*>(e2bs + tt * 64 + jh * 32);
#pragma unroll
        for (int u = 0; u < 4; ++u) {
            uint32_t pk[4];
#pragma unroll
            for (int q = 0; q < 4; ++q) {
                int j = u * 8 + q * 2;
                float2 ev = e2p[u * 4 + q];
                float2 bv = e2bp[u * 4 + q];
                float p0 = fmaxf(ev.x * ci, bv.x * ci2);
                float p1 = fmaxf(ev.y * ci, bv.y * ci2);
                p0 = ((wv >> j) & 1u)       ? p0 : 0.f;
                p1 = ((wv >> (j + 1)) & 1u) ? p1 : 0.f;
                __nv_bfloat162 h2 = __floats2bfloat162_rn(p0, p1);
                pk[q] = *reinterpret_cast<uint32_t*>(&h2);
            }
            *(uint4*)(psW + rt * 36 + jh * 16 + u * 4) =
                make_uint4(pk[0], pk[1], pk[2], pk[3]);
        }
    };

    float acc[9][4];
#pragma unroll
    for (int nt = 0; nt < 9; ++nt)
#pragma unroll
        for (int q = 0; q < 4; ++q) acc[nt][q] = 0.f;

    // prologue: tables + wh(0) arrive, then p(0)
    cpa_wait<0>();
    __syncthreads();
    phase1(0);

    for (int tt = 0; tt < NT; ++tt) {
        cpa_wait<0>();           // wh(tt) copies done
        __syncthreads();         // visible to all; all warps done phase2(tt-1);
                                 // phase1(tt) stores (prev iter) visible
        if (tt + 1 < NT) { issue_tile(tt + 1); cpa_commit(); }

        // ---- A fragments first (reads p(tt)) ----
        uint32_t a[4][4];
#pragma unroll
        for (int kt = 0; kt < 4; ++kt) ldsm4(a[kt], psB + kt * 32);

        // ---- phase 1 of NEXT tile: safe after A-loads (program order),
        //      interleaves with the mma stream below ----
        if (tt + 1 < NT) phase1(tt + 1);

        // ---- phase 2: warp w -> m-tile w, all 9 n-tiles ----
        const int buf = tt & 1;
        const uint32_t whB = whB0 + buf * bufStride;
        const uint32_t dnB = dnB0 + buf * bufStride;
#pragma unroll
        for (int kt = 0; kt < 4; ++kt) {
#pragma unroll
            for (int p = 0; p < 4; ++p) {
                uint32_t b[4];
                ldsm4(b, whB + p * 2304 + kt * 32);
                mma16816(acc[2 * p],     a[kt], b[0], b[1]);
                mma16816(acc[2 * p + 1], a[kt], b[2], b[3]);
            }
            uint32_t d[2];
            ldsm2(d, dnB + kt * 32);
            mma16816(acc[8], a[kt], d[0], d[1]);
        }
    }

    // ---- store partials: slot = h*JS + z ----
    int rA = i0 + w * 16 + r;
    float* pA = part + (((size_t)(h * JS + blockIdx.z)) * GN + rA) * 72;
    float* pB = pA + 8 * 72;
#pragma unroll
    for (int nt = 0; nt < 8; ++nt) {
        int col = nt * 8 + c * 2;
        *(float2*)(pA + col) = make_float2(acc[nt][0], acc[nt][1]);
        *(float2*)(pB + col) = make_float2(acc[nt][2], acc[nt][3]);
    }
    if (c == 0) { pA[64] = acc[8][0]; pB[64] = acc[8][2]; }
}

// ---------------- layer-1 reduce: sum JS1 partials, ELU, bf16 store --------
__global__ void reduce_hbuf_kernel(const float* __restrict__ part,
                                   __nv_bfloat16* __restrict__ outB) {
    int id  = blockIdx.x * 256 + threadIdx.x;
    int row = id >> 8;
    int cp  = (id & 255) * 2;
    int h   = cp >> 6;
    int cl  = cp & 63;
    float n0 = 0.f, n1 = 0.f, d = 0.f;
#pragma unroll
    for (int js = 0; js < JS1; ++js) {
        const float* rp = part + (((size_t)(h * JS1 + js)) * GN + row) * 72;
        float2 nv = *(const float2*)(rp + cl);
        n0 += nv.x; n1 += nv.y; d += rp[64];
    }
    float inv = 1.f / d;
    float v0 = n0 * inv;
    float v1 = n1 * inv;
    v0 = v0 > 0.f ? v0 : (ex2f(v0 * LOG2E) - 1.f);
    v1 = v1 > 0.f ? v1 : (ex2f(v1 * LOG2E) - 1.f);
    *(__nv_bfloat162*)(outB + (size_t)row * FCAT + cp) = __floats2bfloat162_rn(v0, v1);
}

// ---------------- layer-2 reduce: sum JS2 partials + ELU + log_softmax ----
__global__ void reduce_lsm_kernel(const float* __restrict__ part,
                                  float* __restrict__ out) {
    int row = blockIdx.x * 8 + (threadIdx.x >> 5);
    int ln  = threadIdx.x & 31;
    float n0 = 0.f, n1 = 0.f, d = 0.f;
#pragma unroll
    for (int js = 0; js < JS2; ++js) {
        const float* b = part + ((size_t)js * GN + row) * 72;
        n0 += b[ln]; n1 += b[ln + 32]; d += b[64];
    }
    float inv = 1.f / d;
    float v0 = n0 * inv, v1 = n1 * inv;
    v0 = v0 > 0.f ? v0 : (__expf(v0) - 1.f);
    v1 = v1 > 0.f ? v1 : (__expf(v1) - 1.f);
    float mx = fmaxf(v0, v1);
#pragma unroll
    for (int o = 16; o; o >>= 1) mx = fmaxf(mx, __shfl_xor_sync(0xffffffffu, mx, o));
    float s = __expf(v0 - mx) + __expf(v1 - mx);
#pragma unroll
    for (int o = 16; o; o >>= 1) s += __shfl_xor_sync(0xffffffffu, s, o);
    float l = mx + __logf(s);
    out[(size_t)row * 64 + ln]      = v0 - l;
    out[(size_t)row * 64 + ln + 32] = v1 - l;
}

// ---------------- launch ----------------
extern "C" void kernel_launch(void* const* d_in, const int* in_sizes, int n_in,
                              void* d_out, int out_size) {
    const float* x   = (const float*)d_in[0];
    const int*   adj = (const int*)d_in[1];
    const float* W   = (const float*)d_in[2];
    const float* a1  = (const float*)d_in[3];
    const float* a2  = (const float*)d_in[4];
    const float* W2  = (const float*)d_in[5];
    const float* a21 = (const float*)d_in[6];
    const float* a22 = (const float*)d_in[7];
    float* out = (float*)d_out;

    uint32_t* adjbits; unsigned* gmaxi;
    float *wh1, *s1, *s2, *e2, *e2b, *wh2, *s21, *s22, *e22, *e22b, *part;
    __nv_bfloat16 *xb, *Wb, *W2b, *whTb, *hbufb, *whT2b;
    cudaGetSymbolAddress((void**)&adjbits, g_adjbits);
    cudaGetSymbolAddress((void**)&gmaxi, g_gmaxi);
    cudaGetSymbolAddress((void**)&xb,    g_xb);
    cudaGetSymbolAddress((void**)&Wb,    g_Wb);
    cudaGetSymbolAddress((void**)&W2b,   g_W2b);
    cudaGetSymbolAddress((void**)&wh1,   g_wh1);
    cudaGetSymbolAddress((void**)&whTb,  g_whTb);
    cudaGetSymbolAddress((void**)&s1,    g_s1);
    cudaGetSymbolAddress((void**)&s2,    g_s2);
    cudaGetSymbolAddress((void**)&e2,    g_e2);
    cudaGetSymbolAddress((void**)&e2b,   g_e2b);
    cudaGetSymbolAddress((void**)&hbufb, g_hbufb);
    cudaGetSymbolAddress((void**)&wh2,   g_wh2);
    cudaGetSymbolAddress((void**)&whT2b, g_whT2b);
    cudaGetSymbolAddress((void**)&s21,   g_s21);
    cudaGetSymbolAddress((void**)&s22,   g_s22);
    cudaGetSymbolAddress((void**)&e22,   g_e22);
    cudaGetSymbolAddress((void**)&e22b,  g_e22b);
    cudaGetSymbolAddress((void**)&part,  g_part);

    pack_adj_kernel<<<(GN * GN) / 1024, 256>>>(adj, adjbits, gmaxi);
    cvt_all_kernel<<<(GN * FCAT + FCAT * FCAT + HIDF * FCAT) / 512, 256>>>(
        x, xb, W, Wb, W2, W2b);
    gemm_bf16_nt<<<dim3(FCAT / 64, GN / 128), 256>>>(xb, Wb, wh1, FCAT, FCAT);
    scores1_kernel<<<GN / 8, 256>>>(wh1, a1, a2, s1, s2, e2, e2b, gmaxi);
    transpose_cvt_kernel<<<dim3(FCAT / 32, GN / 32), dim3(32, 8)>>>(wh1, whTb, FCAT);
    attn_mma_kernel<JS1><<<dim3(GN / 128, GH, JS1), 256>>>(whTb, s1, e2, e2b,
                                                           gmaxi, adjbits, part);
    reduce_hbuf_kernel<<<GN, 256>>>(part, hbufb);
    gemm_bf16_nt<<<dim3(1, GN / 128), 256>>>(hbufb, W2b, wh2, FCAT, HIDF);
    scores_kernel<<<GN / 8, 256>>>(wh2, HIDF, 1, a21, a22, s21, s22, e22, e22b,
                                   gmaxi + 8);
    transpose_cvt_kernel<<<dim3(HIDF / 32, GN / 32), dim3(32, 8)>>>(wh2, whT2b, HIDF);
    attn_mma_kernel<JS2><<<dim3(GN / 128, 1, JS2), 256>>>(whT2b, s21, e22, e22b,
                                                          gmaxi + 8, adjbits, part);
    reduce_lsm_kernel<<<GN / 8, 256>>>(part, out);
}

// round 14
// speedup vs baseline: 1.0860x; 1.0860x over previous
#include <cuda_runtime.h>
#include <cuda_bf16.h>
#include <stdint.h>

#define GN 4096
#define GH 8
#define FCAT 512
#define HIDF 64
#define ADJW (GN/32)
#define JS1 4
#define JS2 16
#define LOG2E 1.4426950408889634f

// ---------------- scratch ----------------
__device__ uint32_t      g_adjbits[GN * ADJW];
__device__ __nv_bfloat16 g_xb[GN * FCAT];
__device__ __nv_bfloat16 g_Wb[FCAT * FCAT];
__device__ __nv_bfloat16 g_W2b[HIDF * FCAT];
__device__ float         g_wh1[GN * FCAT];
__device__ __nv_bfloat16 g_whTb[FCAT * GN];
__device__ float         g_s1[GH * GN];
__device__ float         g_e2[GH * GN];     // ex2(s2)
__device__ float         g_e2b[GH * GN];    // ex2(0.2*s2)
__device__ unsigned      g_gmaxi[16];
__device__ __nv_bfloat16 g_hbufb[GN * FCAT];
__device__ float         g_wh2[GN * HIDF];
__device__ __nv_bfloat16 g_whT2b[HIDF * GN];
__device__ float         g_s21[GN];
__device__ float         g_e22[GN];
__device__ float         g_e22b[GN];
__device__ float         g_part[32 * GN * 72];    // 32 slots x [row][72]

__device__ __forceinline__ unsigned fenc(float f) {
    unsigned b = __float_as_uint(f);
    return (b & 0x80000000u) ? ~b : (b | 0x80000000u);
}
__device__ __forceinline__ float fdec(unsigned k) {
    return __uint_as_float((k & 0x80000000u) ? (k & 0x7fffffffu) : ~k);
}
__device__ __forceinline__ float ex2f(float x) {
    float y; asm("ex2.approx.f32 %0, %1;" : "=f"(y) : "f"(x)); return y;
}
__device__ __forceinline__ uint32_t sptr(const void* p) {
    return (uint32_t)__cvta_generic_to_shared(p);
}
__device__ __forceinline__ void ldsm4(uint32_t* r, uint32_t a) {
    asm volatile("ldmatrix.sync.aligned.m8n8.x4.shared.b16 {%0,%1,%2,%3}, [%4];"
                 : "=r"(r[0]), "=r"(r[1]), "=r"(r[2]), "=r"(r[3]) : "r"(a));
}
__device__ __forceinline__ void ldsm2(uint32_t* r, uint32_t a) {
    asm volatile("ldmatrix.sync.aligned.m8n8.x2.shared.b16 {%0,%1}, [%2];"
                 : "=r"(r[0]), "=r"(r[1]) : "r"(a));
}
__device__ __forceinline__ void cpa16(uint32_t dst, const void* src) {
    asm volatile("cp.async.cg.shared.global [%0], [%1], 16;" :: "r"(dst), "l"(src));
}
__device__ __forceinline__ void cpa_commit() {
    asm volatile("cp.async.commit_group;");
}
template<int N>
__device__ __forceinline__ void cpa_wait() {
    asm volatile("cp.async.wait_group %0;" :: "n"(N));
}
__device__ __forceinline__ void mma16816(float* d, const uint32_t* a,
                                         uint32_t b0, uint32_t b1) {
    asm volatile(
        "mma.sync.aligned.m16n8k16.row.col.f32.bf16.bf16.f32 "
        "{%0,%1,%2,%3}, {%4,%5,%6,%7}, {%8,%9}, {%0,%1,%2,%3};"
        : "+f"(d[0]), "+f"(d[1]), "+f"(d[2]), "+f"(d[3])
        : "r"(a[0]), "r"(a[1]), "r"(a[2]), "r"(a[3]), "r"(b0), "r"(b1));
}

// ---------------- pack adjacency (4x unrolled) + init gmax ----------------
__global__ void pack_adj_kernel(const int* __restrict__ adj,
                                uint32_t* __restrict__ bits,
                                unsigned* __restrict__ gmaxi) {
    if (blockIdx.x == 0 && threadIdx.x < 16) gmaxi[threadIdx.x] = 0u;
    int wg   = (blockIdx.x * 256 + threadIdx.x) >> 5;
    int lane = threadIdx.x & 31;
    int base = wg * 128;
    int v0 = adj[base + lane];
    int v1 = adj[base + 32 + lane];
    int v2 = adj[base + 64 + lane];
    int v3 = adj[base + 96 + lane];
    uint32_t b[4];
    b[0] = __ballot_sync(0xffffffffu, v0 > 0);
    b[1] = __ballot_sync(0xffffffffu, v1 > 0);
    b[2] = __ballot_sync(0xffffffffu, v2 > 0);
    b[3] = __ballot_sync(0xffffffffu, v3 > 0);
    if (lane < 4) bits[wg * 4 + lane] = b[lane];
}

// ---------------- fp32 -> bf16, all three inputs in one launch ------------
__global__ void cvt_all_kernel(const float* __restrict__ x, __nv_bfloat16* __restrict__ xb,
                               const float* __restrict__ W, __nv_bfloat16* __restrict__ Wb,
                               const float* __restrict__ W2, __nv_bfloat16* __restrict__ W2b) {
    const int NX = GN * FCAT / 2, NW = FCAT * FCAT / 2;
    int id = blockIdx.x * 256 + threadIdx.x;
    const float* src; __nv_bfloat16* dst; int off;
    if (id < NX)           { src = x;  dst = xb;  off = id; }
    else if (id < NX + NW) { src = W;  dst = Wb;  off = id - NX; }
    else                   { src = W2; dst = W2b; off = id - NX - NW; }
    float2 v = *(const float2*)(src + (size_t)off * 2);
    *(__nv_bfloat162*)(dst + (size_t)off * 2) = __floats2bfloat162_rn(v.x, v.y);
}

// ---------------- fp32 [GN][C] -> bf16 transposed [C][GN] ----------------
__global__ void transpose_cvt_kernel(const float* __restrict__ in,
                                     __nv_bfloat16* __restrict__ out, int C) {
    __shared__ float tile[32][33];
    int tx = threadIdx.x, ty = threadIdx.y;
    int c0 = blockIdx.x * 32;
    int r0 = blockIdx.y * 32;
#pragma unroll
    for (int k = 0; k < 4; ++k)
        tile[ty + k * 8][tx] = in[(size_t)(r0 + ty + k * 8) * C + c0 + tx];
    __syncthreads();
#pragma unroll
    for (int k = 0; k < 4; ++k)
        out[(size_t)(c0 + ty + k * 8) * GN + r0 + tx] =
            __float2bfloat16(tile[tx][ty + k * 8]);
}

// ---------------- bf16 NT GEMM + fused scores epilogue --------------------
// Each n-block covers exactly one head's 64 features (n0/64 = head). After
// the C stores, each thread reduces its in-register acc against the head's
// a1/a2 slices (pre-scaled by log2e) and c==0 lanes emit s1/E2/E2b + gmax.
__global__ void __launch_bounds__(256, 3)
gemm_bf16_nt(const __nv_bfloat16* __restrict__ A,
             const __nv_bfloat16* __restrict__ B,
             float* __restrict__ C, int K, int Ncols,
             const float* __restrict__ av1, const float* __restrict__ av2,
             float* __restrict__ s1, float* __restrict__ e2,
             float* __restrict__ e2b, unsigned* __restrict__ gmaxi) {
    __shared__ __nv_bfloat16 As[2][128 * 40];
    __shared__ __nv_bfloat16 Bs[2][64 * 40];
    __shared__ float a1s[64], a2s[64];

    const int t  = threadIdx.x;
    const int m0 = blockIdx.y * 128;
    const int n0 = blockIdx.x * 64;
    const int w = t >> 5, ln = t & 31;
    const int r = ln >> 2, c = ln & 3;

    if (t < 64)       a1s[t]      = av1[n0 + t] * LOG2E;
    else if (t < 128) a2s[t - 64] = av2[n0 + t - 64] * LOG2E;

    const uint32_t aB = sptr(As[0]) + (uint32_t)(((w * 16 + (ln & 15)) * 40 +
                                                  ((ln >> 4) & 1) * 8) * 2);
    const uint32_t bB = sptr(Bs[0]) + (uint32_t)((((ln & 7) + ((ln >> 4) & 1) * 8) * 40 +
                                                  ((ln >> 3) & 1) * 8) * 2);
    const uint32_t ABUF = 128 * 40 * 2;
    const uint32_t BBUF = 64 * 40 * 2;

    float acc[8][4];
#pragma unroll
    for (int nt = 0; nt < 8; ++nt)
#pragma unroll
        for (int q = 0; q < 4; ++q) acc[nt][q] = 0.f;

    auto g_issue = [&](int ki) {
        int buf = ki & 1;
        int kc = ki * 32;
#pragma unroll
        for (int it = 0; it < 2; ++it) {
            int idx = it * 256 + t;
            int row = idx >> 2, u = idx & 3;
            cpa16(sptr(&As[buf][row * 40 + u * 8]),
                  A + (size_t)(m0 + row) * K + kc + u * 8);
        }
        {
            int row = t >> 2, u = t & 3;
            cpa16(sptr(&Bs[buf][row * 40 + u * 8]),
                  B + (size_t)(n0 + row) * K + kc + u * 8);
        }
    };

    const int NK = K / 32;
    g_issue(0); cpa_commit();
    for (int ki = 0; ki < NK; ++ki) {
        if (ki + 1 < NK) { g_issue(ki + 1); cpa_commit(); cpa_wait<1>(); }
        else             { cpa_wait<0>(); }
        __syncthreads();
        const int buf = ki & 1;
#pragma unroll
        for (int kt = 0; kt < 2; ++kt) {
            uint32_t a[4];
            ldsm4(a, aB + buf * ABUF + kt * 32);
#pragma unroll
            for (int p = 0; p < 4; ++p) {
                uint32_t b[4];
                ldsm4(b, bB + buf * BBUF + p * 1280 + kt * 32);
                mma16816(acc[2 * p],     a, b[0], b[1]);
                mma16816(acc[2 * p + 1], a, b[2], b[3]);
            }
        }
        __syncthreads();
    }
    int rA = m0 + w * 16 + r;
#pragma unroll
    for (int nt = 0; nt < 8; ++nt) {
        int col = n0 + nt * 8 + c * 2;
        *(float2*)&C[(size_t)rA * Ncols + col]       = make_float2(acc[nt][0], acc[nt][1]);
        *(float2*)&C[(size_t)(rA + 8) * Ncols + col] = make_float2(acc[nt][2], acc[nt][3]);
    }

    // ---- fused scores: per-thread partial over its 16 cols, 4-lane reduce ----
    float p1A = 0.f, p2A = 0.f, p1B = 0.f, p2B = 0.f;
#pragma unroll
    for (int nt = 0; nt < 8; ++nt) {
        float x1a = a1s[nt * 8 + c * 2], x1b = a1s[nt * 8 + c * 2 + 1];
        float x2a = a2s[nt * 8 + c * 2], x2b = a2s[nt * 8 + c * 2 + 1];
        p1A += acc[nt][0] * x1a + acc[nt][1] * x1b;
        p2A += acc[nt][0] * x2a + acc[nt][1] * x2b;
        p1B += acc[nt][2] * x1a + acc[nt][3] * x1b;
        p2B += acc[nt][2] * x2a + acc[nt][3] * x2b;
    }
#pragma unroll
    for (int o = 2; o; o >>= 1) {
        p1A += __shfl_down_sync(0xffffffffu, p1A, o);
        p2A += __shfl_down_sync(0xffffffffu, p2A, o);
        p1B += __shfl_down_sync(0xffffffffu, p1B, o);
        p2B += __shfl_down_sync(0xffffffffu, p2B, o);
    }
    if (c == 0) {
        int h = n0 >> 6;
        s1[h * GN + rA]      = p1A;
        e2[h * GN + rA]      = ex2f(p2A);
        e2b[h * GN + rA]     = ex2f(0.2f * p2A);
        s1[h * GN + rA + 8]  = p1B;
        e2[h * GN + rA + 8]  = ex2f(p2B);
        e2b[h * GN + rA + 8] = ex2f(0.2f * p2B);
        atomicMax(&gmaxi[h], fenc(fmaxf(p2A, p2B)));
    }
}

// ---------------- fused masked softmax + att@wh (R11 version) -------------
template<int JS>
__global__ void __launch_bounds__(256, 3)
attn_mma_kernel(const __nv_bfloat16* __restrict__ whT,
                const float* __restrict__ s1g,
                const float* __restrict__ e2g, const float* __restrict__ e2bg,
                const unsigned* __restrict__ gmaxi,
                const uint32_t* __restrict__ adjbits,
                float* __restrict__ part) {
    constexpr int NT = (GN / JS) / 64;
    __shared__ __nv_bfloat16 ps[128 * 72];
    __shared__ __nv_bfloat16 whs[2][72 * 72];
    __shared__ float e2t[2][64];
    __shared__ float e2bt[2][64];

    const int t  = threadIdx.x;
    const int i0 = blockIdx.x * 128;
    const int h  = blockIdx.y;
    const int jbase = blockIdx.z * (GN / JS);

    const __nv_bfloat16* whTh = whT + (size_t)h * 64 * GN;
    const float* e2h  = e2g  + h * GN;
    const float* e2bh = e2bg + h * GN;
    uint32_t* psW = reinterpret_cast<uint32_t*>(ps);

#pragma unroll
    for (int b = 0; b < 2; ++b)
        for (int idx = t; idx < 8 * 36; idx += 256) {
            int rr = idx / 36, wd = idx - rr * 36;
            reinterpret_cast<uint32_t*>(whs[b])[(64 + rr) * 36 + wd] =
                (rr == 0) ? 0x3F803F80u : 0u;
        }

    auto issue_tile = [&](int tt) {
        int buf = tt & 1;
        int j0 = jbase + tt * 64;
#pragma unroll
        for (int it = 0; it < 2; ++it) {
            int idx = it * 256 + t;
            int f = idx >> 3, u = idx & 7;
            cpa16(sptr(&whs[buf][f * 72 + u * 8]), whTh + (size_t)f * GN + j0 + u * 8);
        }
        if (t < 16)      cpa16(sptr(&e2t[buf][t * 4]),         e2h  + j0 + t * 4);
        else if (t < 32) cpa16(sptr(&e2bt[buf][(t - 16) * 4]), e2bh + j0 + (t - 16) * 4);
    };

    issue_tile(0);
    cpa_commit();

    const int rt = t >> 1, jh = t & 1;
    const float s1i = s1g[h * GN + i0 + rt];
    const float gme = s1i + fdec(gmaxi[h]);
    const float m   = fmaxf(gme, 0.2f * gme);
    const float ci  = ex2f(s1i - m);
    const float ci2 = ex2f(0.2f * s1i - m);

    const int w = t >> 5, ln = t & 31;
    const int r = ln >> 2, c = ln & 3;

    const uint32_t psB = sptr(ps) + (uint32_t)(((w * 16 + (ln & 15)) * 72 +
                                                ((ln >> 4) & 1) * 8) * 2);
    const uint32_t whB0 = sptr(whs[0]) + (uint32_t)((((ln & 7) + ((ln >> 4) & 1) * 8) * 72 +
                                                     ((ln >> 3) & 1) * 8) * 2);
    const uint32_t dnB0 = sptr(whs[0]) + (uint32_t)(((64 + (ln & 7)) * 72 +
                                                     ((ln >> 3) & 1) * 8) * 2);
    const uint32_t bufStride = (uint32_t)(72 * 72 * 2);

    float acc[9][4];
#pragma unroll
    for (int nt = 0; nt < 9; ++nt)
#pragma unroll
        for (int q = 0; q < 4; ++q) acc[nt][q] = 0.f;

    const uint32_t* adjRow = adjbits + (size_t)(i0 + rt) * ADJW;

    for (int tt = 0; tt < NT; ++tt) {
        cpa_wait<0>();
        __syncthreads();
        if (tt + 1 < NT) { issue_tile(tt + 1); cpa_commit(); }

        const int buf = tt & 1;
        const int j0  = jbase + tt * 64;

        const uint32_t wv = adjRow[(j0 >> 5) + jh];
        const float2* e2p  = reinterpret_cast<const float2*>(e2t[buf]  + jh * 32);
        const float2* e2bp = reinterpret_cast<const float2*>(e2bt[buf] + jh * 32);
#pragma unroll
        for (int u = 0; u < 4; ++u) {
            uint32_t pk[4];
#pragma unroll
            for (int q = 0; q < 4; ++q) {
                int j = u * 8 + q * 2;
                float2 ev = e2p[u * 4 + q];
                float2 bv = e2bp[u * 4 + q];
                float p0 = fmaxf(ev.x * ci, bv.x * ci2);
                float p1 = fmaxf(ev.y * ci, bv.y * ci2);
                p0 = ((wv >> j) & 1u)       ? p0 : 0.f;
                p1 = ((wv >> (j + 1)) & 1u) ? p1 : 0.f;
                __nv_bfloat162 h2 = __floats2bfloat162_rn(p0, p1);
                pk[q] = *reinterpret_cast<uint32_t*>(&h2);
            }
            *(uint4*)(psW + rt * 36 + jh * 16 + u * 4) =
                make_uint4(pk[0], pk[1], pk[2], pk[3]);
        }
        __syncwarp();

        const uint32_t whB = whB0 + buf * bufStride;
        const uint32_t dnB = dnB0 + buf * bufStride;
#pragma unroll
        for (int kt = 0; kt < 4; ++kt) {
            uint32_t a[4];
            ldsm4(a, psB + kt * 32);
#pragma unroll
            for (int p = 0; p < 4; ++p) {
                uint32_t b[4];
                ldsm4(b, whB + p * 2304 + kt * 32);
                mma16816(acc[2 * p],     a, b[0], b[1]);
                mma16816(acc[2 * p + 1], a, b[2], b[3]);
            }
            uint32_t d[2];
            ldsm2(d, dnB + kt * 32);
            mma16816(acc[8], a, d[0], d[1]);
        }
    }

    int rA = i0 + w * 16 + r;
    float* pA = part + (((size_t)(h * JS + blockIdx.z)) * GN + rA) * 72;
    float* pB = pA + 8 * 72;
#pragma unroll
    for (int nt = 0; nt < 8; ++nt) {
        int col = nt * 8 + c * 2;
        *(float2*)(pA + col) = make_float2(acc[nt][0], acc[nt][1]);
        *(float2*)(pB + col) = make_float2(acc[nt][2], acc[nt][3]);
    }
    if (c == 0) { pA[64] = acc[8][0]; pB[64] = acc[8][2]; }
}

// ---------------- layer-1 reduce: sum JS1 partials, ELU, bf16 store --------
__global__ void reduce_hbuf_kernel(const float* __restrict__ part,
                                   __nv_bfloat16* __restrict__ outB) {
    int id  = blockIdx.x * 256 + threadIdx.x;
    int row = id >> 8;
    int cp  = (id & 255) * 2;
    int h   = cp >> 6;
    int cl  = cp & 63;
    float n0 = 0.f, n1 = 0.f, d = 0.f;
#pragma unroll
    for (int js = 0; js < JS1; ++js) {
        const float* rp = part + (((size_t)(h * JS1 + js)) * GN + row) * 72;
        float2 nv = *(const float2*)(rp + cl);
        n0 += nv.x; n1 += nv.y; d += rp[64];
    }
    float inv = 1.f / d;
    float v0 = n0 * inv;
    float v1 = n1 * inv;
    v0 = v0 > 0.f ? v0 : (ex2f(v0 * LOG2E) - 1.f);
    v1 = v1 > 0.f ? v1 : (ex2f(v1 * LOG2E) - 1.f);
    *(__nv_bfloat162*)(outB + (size_t)row * FCAT + cp) = __floats2bfloat162_rn(v0, v1);
}

// ---------------- layer-2 reduce: sum JS2 partials + ELU + log_softmax ----
__global__ void reduce_lsm_kernel(const float* __restrict__ part,
                                  float* __restrict__ out) {
    int row = blockIdx.x * 8 + (threadIdx.x >> 5);
    int ln  = threadIdx.x & 31;
    float n0 = 0.f, n1 = 0.f, d = 0.f;
#pragma unroll
    for (int js = 0; js < JS2; ++js) {
        const float* b = part + ((size_t)js * GN + row) * 72;
        n0 += b[ln]; n1 += b[ln + 32]; d += b[64];
    }
    float inv = 1.f / d;
    float v0 = n0 * inv, v1 = n1 * inv;
    v0 = v0 > 0.f ? v0 : (__expf(v0) - 1.f);
    v1 = v1 > 0.f ? v1 : (__expf(v1) - 1.f);
    float mx = fmaxf(v0, v1);
#pragma unroll
    for (int o = 16; o; o >>= 1) mx = fmaxf(mx, __shfl_xor_sync(0xffffffffu, mx, o));
    float s = __expf(v0 - mx) + __expf(v1 - mx);
#pragma unroll
    for (int o = 16; o; o >>= 1) s += __shfl_xor_sync(0xffffffffu, s, o);
    float l = mx + __logf(s);
    out[(size_t)row * 64 + ln]      = v0 - l;
    out[(size_t)row * 64 + ln + 32] = v1 - l;
}

// ---------------- launch ----------------
extern "C" void kernel_launch(void* const* d_in, const int* in_sizes, int n_in,
                              void* d_out, int out_size) {
    const float* x   = (const float*)d_in[0];
    const int*   adj = (const int*)d_in[1];
    const float* W   = (const float*)d_in[2];
    const float* a1  = (const float*)d_in[3];
    const float* a2  = (const float*)d_in[4];
    const float* W2  = (const float*)d_in[5];
    const float* a21 = (const float*)d_in[6];
    const float* a22 = (const float*)d_in[7];
    float* out = (float*)d_out;

    uint32_t* adjbits; unsigned* gmaxi;
    float *wh1, *s1, *e2, *e2b, *wh2, *s21, *e22, *e22b, *part;
    __nv_bfloat16 *xb, *Wb, *W2b, *whTb, *hbufb, *whT2b;
    cudaGetSymbolAddress((void**)&adjbits, g_adjbits);
    cudaGetSymbolAddress((void**)&gmaxi, g_gmaxi);
    cudaGetSymbolAddress((void**)&xb,    g_xb);
    cudaGetSymbolAddress((void**)&Wb,    g_Wb);
    cudaGetSymbolAddress((void**)&W2b,   g_W2b);
    cudaGetSymbolAddress((void**)&wh1,   g_wh1);
    cudaGetSymbolAddress((void**)&whTb,  g_whTb);
    cudaGetSymbolAddress((void**)&s1,    g_s1);
    cudaGetSymbolAddress((void**)&e2,    g_e2);
    cudaGetSymbolAddress((void**)&e2b,   g_e2b);
    cudaGetSymbolAddress((void**)&hbufb, g_hbufb);
    cudaGetSymbolAddress((void**)&wh2,   g_wh2);
    cudaGetSymbolAddress((void**)&whT2b, g_whT2b);
    cudaGetSymbolAddress((void**)&s21,   g_s21);
    cudaGetSymbolAddress((void**)&e22,   g_e22);
    cudaGetSymbolAddress((void**)&e22b,  g_e22b);
    cudaGetSymbolAddress((void**)&part,  g_part);

    pack_adj_kernel<<<(GN * GN) / 1024, 256>>>(adj, adjbits, gmaxi);
    cvt_all_kernel<<<(GN * FCAT + FCAT * FCAT + HIDF * FCAT) / 512, 256>>>(
        x, xb, W, Wb, W2, W2b);
    // layer-1 GEMM with fused scores epilogue
    gemm_bf16_nt<<<dim3(FCAT / 64, GN / 128), 256>>>(xb, Wb, wh1, FCAT, FCAT,
                                                     a1, a2, s1, e2, e2b, gmaxi);
    transpose_cvt_kernel<<<dim3(FCAT / 32, GN / 32), dim3(32, 8)>>>(wh1, whTb, FCAT);
    attn_mma_kernel<JS1><<<dim3(GN / 128, GH, JS1), 256>>>(whTb, s1, e2, e2b,
                                                           gmaxi, adjbits, part);
    reduce_hbuf_kernel<<<GN, 256>>>(part, hbufb);
    // layer-2 GEMM with fused scores epilogue
    gemm_bf16_nt<<<dim3(1, GN / 128), 256>>>(hbufb, W2b, wh2, FCAT, HIDF,
                                             a21, a22, s21, e22, e22b, gmaxi + 8);
    transpose_cvt_kernel<<<dim3(HIDF / 32, GN / 32), dim3(32, 8)>>>(wh2, whT2b, HIDF);
    attn_mma_kernel<JS2><<<dim3(GN / 128, 1, JS2), 256>>>(whT2b, s21, e22, e22b,
                                                          gmaxi + 8, adjbits, part);
    reduce_lsm_kernel<<<GN / 8, 256>>>(part, out);
}

// round 15
// speedup vs baseline: 1.1262x; 1.0371x over previous
#include <cuda_runtime.h>
#include <cuda_bf16.h>
#include <stdint.h>

#define GN 4096
#define GH 8
#define FCAT 512
#define HIDF 64
#define ADJW (GN/32)
#define JS1 4
#define JS2 16
#define LOG2E 1.4426950408889634f

// ---------------- scratch ----------------
__device__ uint32_t      g_adjbits[GN * ADJW];
__device__ __nv_bfloat16 g_xb[GN * FCAT];
__device__ __nv_bfloat16 g_Wb[FCAT * FCAT];
__device__ __nv_bfloat16 g_W2b[HIDF * FCAT];
__device__ __nv_bfloat16 g_whTb[FCAT * GN];
__device__ float         g_s1[GH * GN];
__device__ float         g_e2[GH * GN];     // ex2(s2)
__device__ float         g_e2b[GH * GN];    // ex2(0.2*s2)
__device__ unsigned      g_gmaxi[16];
__device__ __nv_bfloat16 g_hbufb[GN * FCAT];
__device__ __nv_bfloat16 g_whT2b[HIDF * GN];
__device__ float         g_s21[GN];
__device__ float         g_e22[GN];
__device__ float         g_e22b[GN];
__device__ float         g_part[32 * GN * 72];    // 32 slots x [row][72]

__device__ __forceinline__ unsigned fenc(float f) {
    unsigned b = __float_as_uint(f);
    return (b & 0x80000000u) ? ~b : (b | 0x80000000u);
}
__device__ __forceinline__ float fdec(unsigned k) {
    return __uint_as_float((k & 0x80000000u) ? (k & 0x7fffffffu) : ~k);
}
__device__ __forceinline__ float ex2f(float x) {
    float y; asm("ex2.approx.f32 %0, %1;" : "=f"(y) : "f"(x)); return y;
}
__device__ __forceinline__ uint32_t sptr(const void* p) {
    return (uint32_t)__cvta_generic_to_shared(p);
}
__device__ __forceinline__ void ldsm4(uint32_t* r, uint32_t a) {
    asm volatile("ldmatrix.sync.aligned.m8n8.x4.shared.b16 {%0,%1,%2,%3}, [%4];"
                 : "=r"(r[0]), "=r"(r[1]), "=r"(r[2]), "=r"(r[3]) : "r"(a));
}
__device__ __forceinline__ void ldsm2(uint32_t* r, uint32_t a) {
    asm volatile("ldmatrix.sync.aligned.m8n8.x2.shared.b16 {%0,%1}, [%2];"
                 : "=r"(r[0]), "=r"(r[1]) : "r"(a));
}
__device__ __forceinline__ void cpa16(uint32_t dst, const void* src) {
    asm volatile("cp.async.cg.shared.global [%0], [%1], 16;" :: "r"(dst), "l"(src));
}
__device__ __forceinline__ void cpa_commit() {
    asm volatile("cp.async.commit_group;");
}
template<int N>
__device__ __forceinline__ void cpa_wait() {
    asm volatile("cp.async.wait_group %0;" :: "n"(N));
}
__device__ __forceinline__ void mma16816(float* d, const uint32_t* a,
                                         uint32_t b0, uint32_t b1) {
    asm volatile(
        "mma.sync.aligned.m16n8k16.row.col.f32.bf16.bf16.f32 "
        "{%0,%1,%2,%3}, {%4,%5,%6,%7}, {%8,%9}, {%0,%1,%2,%3};"
        : "+f"(d[0]), "+f"(d[1]), "+f"(d[2]), "+f"(d[3])
        : "r"(a[0]), "r"(a[1]), "r"(a[2]), "r"(a[3]), "r"(b0), "r"(b1));
}

// ---------------- pack adjacency (4x unrolled) + init gmax ----------------
__global__ void pack_adj_kernel(const int* __restrict__ adj,
                                uint32_t* __restrict__ bits,
                                unsigned* __restrict__ gmaxi) {
    if (blockIdx.x == 0 && threadIdx.x < 16) gmaxi[threadIdx.x] = 0u;
    int wg   = (blockIdx.x * 256 + threadIdx.x) >> 5;
    int lane = threadIdx.x & 31;
    int base = wg * 128;
    int v0 = adj[base + lane];
    int v1 = adj[base + 32 + lane];
    int v2 = adj[base + 64 + lane];
    int v3 = adj[base + 96 + lane];
    uint32_t b[4];
    b[0] = __ballot_sync(0xffffffffu, v0 > 0);
    b[1] = __ballot_sync(0xffffffffu, v1 > 0);
    b[2] = __ballot_sync(0xffffffffu, v2 > 0);
    b[3] = __ballot_sync(0xffffffffu, v3 > 0);
    if (lane < 4) bits[wg * 4 + lane] = b[lane];
}

// ---------------- fp32 -> bf16, all three inputs in one launch ------------
__global__ void cvt_all_kernel(const float* __restrict__ x, __nv_bfloat16* __restrict__ xb,
                               const float* __restrict__ W, __nv_bfloat16* __restrict__ Wb,
                               const float* __restrict__ W2, __nv_bfloat16* __restrict__ W2b) {
    const int NX = GN * FCAT / 2, NW = FCAT * FCAT / 2;
    int id = blockIdx.x * 256 + threadIdx.x;
    const float* src; __nv_bfloat16* dst; int off;
    if (id < NX)           { src = x;  dst = xb;  off = id; }
    else if (id < NX + NW) { src = W;  dst = Wb;  off = id - NX; }
    else                   { src = W2; dst = W2b; off = id - NX - NW; }
    float2 v = *(const float2*)(src + (size_t)off * 2);
    *(__nv_bfloat162*)(dst + (size_t)off * 2) = __floats2bfloat162_rn(v.x, v.y);
}

// ---------------- bf16 NT GEMM + fused scores + fused transposed output ---
// n-block = one head's 64 features. Outputs ONLY: whT bf16 [col][j] (via smem
// transpose staging in the dead A buffers) and s1/E2/E2b/gmax. No fp32 C.
__global__ void __launch_bounds__(256, 3)
gemm_bf16_nt(const __nv_bfloat16* __restrict__ A,
             const __nv_bfloat16* __restrict__ B,
             __nv_bfloat16* __restrict__ whTg, int K,
             const float* __restrict__ av1, const float* __restrict__ av2,
             float* __restrict__ s1, float* __restrict__ e2,
             float* __restrict__ e2b, unsigned* __restrict__ gmaxi) {
    __shared__ __nv_bfloat16 As[2][128 * 40];
    __shared__ __nv_bfloat16 Bs[2][64 * 40];
    __shared__ float a1s[64], a2s[64];

    const int t  = threadIdx.x;
    const int m0 = blockIdx.y * 128;
    const int n0 = blockIdx.x * 64;
    const int w = t >> 5, ln = t & 31;
    const int r = ln >> 2, c = ln & 3;

    if (t < 64)       a1s[t]      = av1[n0 + t] * LOG2E;
    else if (t < 128) a2s[t - 64] = av2[n0 + t - 64] * LOG2E;

    const uint32_t aB = sptr(As[0]) + (uint32_t)(((w * 16 + (ln & 15)) * 40 +
                                                  ((ln >> 4) & 1) * 8) * 2);
    const uint32_t bB = sptr(Bs[0]) + (uint32_t)((((ln & 7) + ((ln >> 4) & 1) * 8) * 40 +
                                                  ((ln >> 3) & 1) * 8) * 2);
    const uint32_t ABUF = 128 * 40 * 2;
    const uint32_t BBUF = 64 * 40 * 2;

    float acc[8][4];
#pragma unroll
    for (int nt = 0; nt < 8; ++nt)
#pragma unroll
        for (int q = 0; q < 4; ++q) acc[nt][q] = 0.f;

    auto g_issue = [&](int ki) {
        int buf = ki & 1;
        int kc = ki * 32;
#pragma unroll
        for (int it = 0; it < 2; ++it) {
            int idx = it * 256 + t;
            int row = idx >> 2, u = idx & 3;
            cpa16(sptr(&As[buf][row * 40 + u * 8]),
                  A + (size_t)(m0 + row) * K + kc + u * 8);
        }
        {
            int row = t >> 2, u = t & 3;
            cpa16(sptr(&Bs[buf][row * 40 + u * 8]),
                  B + (size_t)(n0 + row) * K + kc + u * 8);
        }
    };

    const int NK = K / 32;
    g_issue(0); cpa_commit();
    for (int ki = 0; ki < NK; ++ki) {
        if (ki + 1 < NK) { g_issue(ki + 1); cpa_commit(); cpa_wait<1>(); }
        else             { cpa_wait<0>(); }
        __syncthreads();
        const int buf = ki & 1;
#pragma unroll
        for (int kt = 0; kt < 2; ++kt) {
            uint32_t a[4];
            ldsm4(a, aB + buf * ABUF + kt * 32);
#pragma unroll
            for (int p = 0; p < 4; ++p) {
                uint32_t b[4];
                ldsm4(b, bB + buf * BBUF + p * 1280 + kt * 32);
                mma16816(acc[2 * p],     a, b[0], b[1]);
                mma16816(acc[2 * p + 1], a, b[2], b[3]);
            }
        }
        __syncthreads();
    }

    // ---- fused scores: per-thread partial over its 16 cols, 4-lane reduce ----
    const int rA = m0 + w * 16 + r;
    float p1A = 0.f, p2A = 0.f, p1B = 0.f, p2B = 0.f;
#pragma unroll
    for (int nt = 0; nt < 8; ++nt) {
        float x1a = a1s[nt * 8 + c * 2], x1b = a1s[nt * 8 + c * 2 + 1];
        float x2a = a2s[nt * 8 + c * 2], x2b = a2s[nt * 8 + c * 2 + 1];
        p1A += acc[nt][0] * x1a + acc[nt][1] * x1b;
        p2A += acc[nt][0] * x2a + acc[nt][1] * x2b;
        p1B += acc[nt][2] * x1a + acc[nt][3] * x1b;
        p2B += acc[nt][2] * x2a + acc[nt][3] * x2b;
    }
#pragma unroll
    for (int o = 2; o; o >>= 1) {
        p1A += __shfl_down_sync(0xffffffffu, p1A, o);
        p2A += __shfl_down_sync(0xffffffffu, p2A, o);
        p1B += __shfl_down_sync(0xffffffffu, p1B, o);
        p2B += __shfl_down_sync(0xffffffffu, p2B, o);
    }
    if (c == 0) {
        int h = n0 >> 6;
        s1[h * GN + rA]      = p1A;
        e2[h * GN + rA]      = ex2f(p2A);
        e2b[h * GN + rA]     = ex2f(0.2f * p2A);
        s1[h * GN + rA + 8]  = p1B;
        e2[h * GN + rA + 8]  = ex2f(p2B);
        e2b[h * GN + rA + 8] = ex2f(0.2f * p2B);
        atomicMax(&gmaxi[h], fenc(fmaxf(p2A, p2B)));
    }

    // ---- fused transposed bf16 output via smem staging (reuse As) ----
    // Ts[col][rowL], stride 136 bf16 (272B, 16B-aligned). 64*136*2 = 17.4KB
    // fits in As (20.4KB). Mainloop's final syncthreads freed the buffers.
    __nv_bfloat16* Ts = As[0];
    {
        int rl = w * 16 + r;
#pragma unroll
        for (int nt = 0; nt < 8; ++nt) {
            int cc = nt * 8 + c * 2;
            Ts[cc * 136 + rl]           = __float2bfloat16(acc[nt][0]);
            Ts[(cc + 1) * 136 + rl]     = __float2bfloat16(acc[nt][1]);
            Ts[cc * 136 + rl + 8]       = __float2bfloat16(acc[nt][2]);
            Ts[(cc + 1) * 136 + rl + 8] = __float2bfloat16(acc[nt][3]);
        }
    }
    __syncthreads();
    // 64 T-rows x 128 bf16 = 1024 x 16B chunks, coalesced out
#pragma unroll
    for (int it = 0; it < 4; ++it) {
        int idx = it * 256 + t;
        int col = idx >> 4, u = idx & 15;
        uint4 v = *(const uint4*)(Ts + col * 136 + u * 8);
        *(uint4*)(whTg + (size_t)(n0 + col) * GN + m0 + u * 8) = v;
    }
}

// ---------------- fused masked softmax + att@wh -------------
template<int JS>
__global__ void __launch_bounds__(256, 3)
attn_mma_kernel(const __nv_bfloat16* __restrict__ whT,
                const float* __restrict__ s1g,
                const float* __restrict__ e2g, const float* __restrict__ e2bg,
                const unsigned* __restrict__ gmaxi,
                const uint32_t* __restrict__ adjbits,
                float* __restrict__ part) {
    constexpr int NT = (GN / JS) / 64;
    __shared__ __nv_bfloat16 ps[128 * 72];
    __shared__ __nv_bfloat16 whs[2][72 * 72];
    __shared__ float e2t[2][64];
    __shared__ float e2bt[2][64];

    const int t  = threadIdx.x;
    const int i0 = blockIdx.x * 128;
    const int h  = blockIdx.y;
    const int jbase = blockIdx.z * (GN / JS);

    const __nv_bfloat16* whTh = whT + (size_t)h * 64 * GN;
    const float* e2h  = e2g  + h * GN;
    const float* e2bh = e2bg + h * GN;
    uint32_t* psW = reinterpret_cast<uint32_t*>(ps);

#pragma unroll
    for (int b = 0; b < 2; ++b)
        for (int idx = t; idx < 8 * 36; idx += 256) {
            int rr = idx / 36, wd = idx - rr * 36;
            reinterpret_cast<uint32_t*>(whs[b])[(64 + rr) * 36 + wd] =
                (rr == 0) ? 0x3F803F80u : 0u;
        }

    auto issue_tile = [&](int tt) {
        int buf = tt & 1;
        int j0 = jbase + tt * 64;
#pragma unroll
        for (int it = 0; it < 2; ++it) {
            int idx = it * 256 + t;
            int f = idx >> 3, u = idx & 7;
            cpa16(sptr(&whs[buf][f * 72 + u * 8]), whTh + (size_t)f * GN + j0 + u * 8);
        }
        if (t < 16)      cpa16(sptr(&e2t[buf][t * 4]),         e2h  + j0 + t * 4);
        else if (t < 32) cpa16(sptr(&e2bt[buf][(t - 16) * 4]), e2bh + j0 + (t - 16) * 4);
    };

    issue_tile(0);
    cpa_commit();

    const int rt = t >> 1, jh = t & 1;
    const float s1i = s1g[h * GN + i0 + rt];
    const float gme = s1i + fdec(gmaxi[h]);
    const float m   = fmaxf(gme, 0.2f * gme);
    const float ci  = ex2f(s1i - m);
    const float ci2 = ex2f(0.2f * s1i - m);

    const int w = t >> 5, ln = t & 31;
    const int r = ln >> 2, c = ln & 3;

    const uint32_t psB = sptr(ps) + (uint32_t)(((w * 16 + (ln & 15)) * 72 +
                                                ((ln >> 4) & 1) * 8) * 2);
    const uint32_t whB0 = sptr(whs[0]) + (uint32_t)((((ln & 7) + ((ln >> 4) & 1) * 8) * 72 +
                                                     ((ln >> 3) & 1) * 8) * 2);
    const uint32_t dnB0 = sptr(whs[0]) + (uint32_t)(((64 + (ln & 7)) * 72 +
                                                     ((ln >> 3) & 1) * 8) * 2);
    const uint32_t bufStride = (uint32_t)(72 * 72 * 2);

    float acc[9][4];
#pragma unroll
    for (int nt = 0; nt < 9; ++nt)
#pragma unroll
        for (int q = 0; q < 4; ++q) acc[nt][q] = 0.f;

    const uint32_t* adjRow = adjbits + (size_t)(i0 + rt) * ADJW;

    for (int tt = 0; tt < NT; ++tt) {
        cpa_wait<0>();
        __syncthreads();
        if (tt + 1 < NT) { issue_tile(tt + 1); cpa_commit(); }

        const int buf = tt & 1;
        const int j0  = jbase + tt * 64;

        const uint32_t wv = adjRow[(j0 >> 5) + jh];
        const float2* e2p  = reinterpret_cast<const float2*>(e2t[buf]  + jh * 32);
        const float2* e2bp = reinterpret_cast<const float2*>(e2bt[buf] + jh * 32);
#pragma unroll
        for (int u = 0; u < 4; ++u) {
            uint32_t pk[4];
#pragma unroll
            for (int q = 0; q < 4; ++q) {
                int j = u * 8 + q * 2;
                float2 ev = e2p[u * 4 + q];
                float2 bv = e2bp[u * 4 + q];
                float p0 = fmaxf(ev.x * ci, bv.x * ci2);
                float p1 = fmaxf(ev.y * ci, bv.y * ci2);
                p0 = ((wv >> j) & 1u)       ? p0 : 0.f;
                p1 = ((wv >> (j + 1)) & 1u) ? p1 : 0.f;
                __nv_bfloat162 h2 = __floats2bfloat162_rn(p0, p1);
                pk[q] = *reinterpret_cast<uint32_t*>(&h2);
            }
            *(uint4*)(psW + rt * 36 + jh * 16 + u * 4) =
                make_uint4(pk[0], pk[1], pk[2], pk[3]);
        }
        __syncwarp();

        const uint32_t whB = whB0 + buf * bufStride;
        const uint32_t dnB = dnB0 + buf * bufStride;
#pragma unroll
        for (int kt = 0; kt < 4; ++kt) {
            uint32_t a[4];
            ldsm4(a, psB + kt * 32);
#pragma unroll
            for (int p = 0; p < 4; ++p) {
                uint32_t b[4];
                ldsm4(b, whB + p * 2304 + kt * 32);
                mma16816(acc[2 * p],     a, b[0], b[1]);
                mma16816(acc[2 * p + 1], a, b[2], b[3]);
            }
            uint32_t d[2];
            ldsm2(d, dnB + kt * 32);
            mma16816(acc[8], a, d[0], d[1]);
        }
    }

    int rA = i0 + w * 16 + r;
    float* pA = part + (((size_t)(h * JS + blockIdx.z)) * GN + rA) * 72;
    float* pB = pA + 8 * 72;
#pragma unroll
    for (int nt = 0; nt < 8; ++nt) {
        int col = nt * 8 + c * 2;
        *(float2*)(pA + col) = make_float2(acc[nt][0], acc[nt][1]);
        *(float2*)(pB + col) = make_float2(acc[nt][2], acc[nt][3]);
    }
    if (c == 0) { pA[64] = acc[8][0]; pB[64] = acc[8][2]; }
}

// ---------------- layer-1 reduce: sum JS1 partials, ELU, bf16 store --------
__global__ void reduce_hbuf_kernel(const float* __restrict__ part,
                                   __nv_bfloat16* __restrict__ outB) {
    int id  = blockIdx.x * 256 + threadIdx.x;
    int row = id >> 8;
    int cp  = (id & 255) * 2;
    int h   = cp >> 6;
    int cl  = cp & 63;
    float n0 = 0.f, n1 = 0.f, d = 0.f;
#pragma unroll
    for (int js = 0; js < JS1; ++js) {
        const float* rp = part + (((size_t)(h * JS1 + js)) * GN + row) * 72;
        float2 nv = *(const float2*)(rp + cl);
        n0 += nv.x; n1 += nv.y; d += rp[64];
    }
    float inv = 1.f / d;
    float v0 = n0 * inv;
    float v1 = n1 * inv;
    v0 = v0 > 0.f ? v0 : (ex2f(v0 * LOG2E) - 1.f);
    v1 = v1 > 0.f ? v1 : (ex2f(v1 * LOG2E) - 1.f);
    *(__nv_bfloat162*)(outB + (size_t)row * FCAT + cp) = __floats2bfloat162_rn(v0, v1);
}

// ---------------- layer-2 reduce: sum JS2 partials + ELU + log_softmax ----
__global__ void reduce_lsm_kernel(const float* __restrict__ part,
                                  float* __restrict__ out) {
    int row = blockIdx.x * 8 + (threadIdx.x >> 5);
    int ln  = threadIdx.x & 31;
    float n0 = 0.f, n1 = 0.f, d = 0.f;
#pragma unroll
    for (int js = 0; js < JS2; ++js) {
        const float* b = part + ((size_t)js * GN + row) * 72;
        n0 += b[ln]; n1 += b[ln + 32]; d += b[64];
    }
    float inv = 1.f / d;
    float v0 = n0 * inv, v1 = n1 * inv;
    v0 = v0 > 0.f ? v0 : (__expf(v0) - 1.f);
    v1 = v1 > 0.f ? v1 : (__expf(v1) - 1.f);
    float mx = fmaxf(v0, v1);
#pragma unroll
    for (int o = 16; o; o >>= 1) mx = fmaxf(mx, __shfl_xor_sync(0xffffffffu, mx, o));
    float s = __expf(v0 - mx) + __expf(v1 - mx);
#pragma unroll
    for (int o = 16; o; o >>= 1) s += __shfl_xor_sync(0xffffffffu, s, o);
    float l = mx + __logf(s);
    out[(size_t)row * 64 + ln]      = v0 - l;
    out[(size_t)row * 64 + ln + 32] = v1 - l;
}

// ---------------- launch ----------------
extern "C" void kernel_launch(void* const* d_in, const int* in_sizes, int n_in,
                              void* d_out, int out_size) {
    const float* x   = (const float*)d_in[0];
    const int*   adj = (const int*)d_in[1];
    const float* W   = (const float*)d_in[2];
    const float* a1  = (const float*)d_in[3];
    const float* a2  = (const float*)d_in[4];
    const float* W2  = (const float*)d_in[5];
    const float* a21 = (const float*)d_in[6];
    const float* a22 = (const float*)d_in[7];
    float* out = (float*)d_out;

    uint32_t* adjbits; unsigned* gmaxi;
    float *s1, *e2, *e2b, *s21, *e22, *e22b, *part;
    __nv_bfloat16 *xb, *Wb, *W2b, *whTb, *hbufb, *whT2b;
    cudaGetSymbolAddress((void**)&adjbits, g_adjbits);
    cudaGetSymbolAddress((void**)&gmaxi, g_gmaxi);
    cudaGetSymbolAddress((void**)&xb,    g_xb);
    cudaGetSymbolAddress((void**)&Wb,    g_Wb);
    cudaGetSymbolAddress((void**)&W2b,   g_W2b);
    cudaGetSymbolAddress((void**)&whTb,  g_whTb);
    cudaGetSymbolAddress((void**)&s1,    g_s1);
    cudaGetSymbolAddress((void**)&e2,    g_e2);
    cudaGetSymbolAddress((void**)&e2b,   g_e2b);
    cudaGetSymbolAddress((void**)&hbufb, g_hbufb);
    cudaGetSymbolAddress((void**)&whT2b, g_whT2b);
    cudaGetSymbolAddress((void**)&s21,   g_s21);
    cudaGetSymbolAddress((void**)&e22,   g_e22);
    cudaGetSymbolAddress((void**)&e22b,  g_e22b);
    cudaGetSymbolAddress((void**)&part,  g_part);

    pack_adj_kernel<<<(GN * GN) / 1024, 256>>>(adj, adjbits, gmaxi);
    cvt_all_kernel<<<(GN * FCAT + FCAT * FCAT + HIDF * FCAT) / 512, 256>>>(
        x, xb, W, Wb, W2, W2b);
    // layer-1 GEMM: outputs whT bf16 + scores (no fp32 intermediate)
    gemm_bf16_nt<<<dim3(FCAT / 64, GN / 128), 256>>>(xb, Wb, whTb, FCAT,
                                                     a1, a2, s1, e2, e2b, gmaxi);
    attn_mma_kernel<JS1><<<dim3(GN / 128, GH, JS1), 256>>>(whTb, s1, e2, e2b,
                                                           gmaxi, adjbits, part);
    reduce_hbuf_kernel<<<GN, 256>>>(part, hbufb);
    // layer-2 GEMM: same fused outputs
    gemm_bf16_nt<<<dim3(1, GN / 128), 256>>>(hbufb, W2b, whT2b, FCAT,
                                             a21, a22, s21, e22, e22b, gmaxi + 8);
    attn_mma_kernel<JS2><<<dim3(GN / 128, 1, JS2), 256>>>(whT2b, s21, e22, e22b,
                                                          gmaxi + 8, adjbits, part);
    reduce_lsm_kernel<<<GN / 8, 256>>>(part, out);
}

// round 16
// speedup vs baseline: 1.3239x; 1.1755x over previous
#include <cuda_runtime.h>
#include <cuda_bf16.h>
#include <stdint.h>

#define GN 4096
#define GH 8
#define FCAT 512
#define HIDF 64
#define ADJW (GN/32)
#define JS1 4
#define JS2 16
#define LOG2E 1.4426950408889634f

// ---------------- scratch ----------------
__device__ uint32_t      g_adjbits[GN * ADJW];
__device__ __nv_bfloat16 g_xb[GN * FCAT];
__device__ __nv_bfloat16 g_Wb[FCAT * FCAT];
__device__ __nv_bfloat16 g_W2b[HIDF * FCAT];
__device__ __nv_bfloat16 g_whTb[FCAT * GN];
__device__ float         g_s1[GH * GN];
__device__ float         g_e2[GH * GN];     // ex2(s2)
__device__ float         g_e2b[GH * GN];    // ex2(0.2*s2)
__device__ unsigned      g_gmaxi[16];
__device__ __nv_bfloat16 g_hbufb[GN * FCAT];
__device__ __nv_bfloat16 g_whT2b[HIDF * GN];
__device__ float         g_s21[GN];
__device__ float         g_e22[GN];
__device__ float         g_e22b[GN];
__device__ float         g_part[32 * GN * 72];    // 32 slots x [row][72]

__device__ __forceinline__ unsigned fenc(float f) {
    unsigned b = __float_as_uint(f);
    return (b & 0x80000000u) ? ~b : (b | 0x80000000u);
}
__device__ __forceinline__ float fdec(unsigned k) {
    return __uint_as_float((k & 0x80000000u) ? (k & 0x7fffffffu) : ~k);
}
__device__ __forceinline__ float ex2f(float x) {
    float y; asm("ex2.approx.f32 %0, %1;" : "=f"(y) : "f"(x)); return y;
}
__device__ __forceinline__ uint32_t sptr(const void* p) {
    return (uint32_t)__cvta_generic_to_shared(p);
}
__device__ __forceinline__ void ldsm4(uint32_t* r, uint32_t a) {
    asm volatile("ldmatrix.sync.aligned.m8n8.x4.shared.b16 {%0,%1,%2,%3}, [%4];"
                 : "=r"(r[0]), "=r"(r[1]), "=r"(r[2]), "=r"(r[3]) : "r"(a));
}
__device__ __forceinline__ void ldsm2(uint32_t* r, uint32_t a) {
    asm volatile("ldmatrix.sync.aligned.m8n8.x2.shared.b16 {%0,%1}, [%2];"
                 : "=r"(r[0]), "=r"(r[1]) : "r"(a));
}
__device__ __forceinline__ void cpa16(uint32_t dst, const void* src) {
    asm volatile("cp.async.cg.shared.global [%0], [%1], 16;" :: "r"(dst), "l"(src));
}
__device__ __forceinline__ void cpa_commit() {
    asm volatile("cp.async.commit_group;");
}
template<int N>
__device__ __forceinline__ void cpa_wait() {
    asm volatile("cp.async.wait_group %0;" :: "n"(N));
}
__device__ __forceinline__ void mma16816(float* d, const uint32_t* a,
                                         uint32_t b0, uint32_t b1) {
    asm volatile(
        "mma.sync.aligned.m16n8k16.row.col.f32.bf16.bf16.f32 "
        "{%0,%1,%2,%3}, {%4,%5,%6,%7}, {%8,%9}, {%0,%1,%2,%3};"
        : "+f"(d[0]), "+f"(d[1]), "+f"(d[2]), "+f"(d[3])
        : "r"(a[0]), "r"(a[1]), "r"(a[2]), "r"(a[3]), "r"(b0), "r"(b1));
}

// ---------------- pack adjacency (4x unrolled) + init gmax ----------------
__global__ void pack_adj_kernel(const int* __restrict__ adj,
                                uint32_t* __restrict__ bits,
                                unsigned* __restrict__ gmaxi) {
    if (blockIdx.x == 0 && threadIdx.x < 16) gmaxi[threadIdx.x] = 0u;
    int wg   = (blockIdx.x * 256 + threadIdx.x) >> 5;
    int lane = threadIdx.x & 31;
    int base = wg * 128;
    int v0 = adj[base + lane];
    int v1 = adj[base + 32 + lane];
    int v2 = adj[base + 64 + lane];
    int v3 = adj[base + 96 + lane];
    uint32_t b[4];
    b[0] = __ballot_sync(0xffffffffu, v0 > 0);
    b[1] = __ballot_sync(0xffffffffu, v1 > 0);
    b[2] = __ballot_sync(0xffffffffu, v2 > 0);
    b[3] = __ballot_sync(0xffffffffu, v3 > 0);
    if (lane < 4) bits[wg * 4 + lane] = b[lane];
}

// ---------------- fp32 -> bf16, all three inputs in one launch ------------
__global__ void cvt_all_kernel(const float* __restrict__ x, __nv_bfloat16* __restrict__ xb,
                               const float* __restrict__ W, __nv_bfloat16* __restrict__ Wb,
                               const float* __restrict__ W2, __nv_bfloat16* __restrict__ W2b) {
    const int NX = GN * FCAT / 2, NW = FCAT * FCAT / 2;
    int id = blockIdx.x * 256 + threadIdx.x;
    const float* src; __nv_bfloat16* dst; int off;
    if (id < NX)           { src = x;  dst = xb;  off = id; }
    else if (id < NX + NW) { src = W;  dst = Wb;  off = id - NX; }
    else                   { src = W2; dst = W2b; off = id - NX - NW; }
    float2 v = *(const float2*)(src + (size_t)off * 2);
    *(__nv_bfloat162*)(dst + (size_t)off * 2) = __floats2bfloat162_rn(v.x, v.y);
}

// ---------------- bf16 NT GEMM + fused scores + fused transposed output ---
__global__ void __launch_bounds__(256, 3)
gemm_bf16_nt(const __nv_bfloat16* __restrict__ A,
             const __nv_bfloat16* __restrict__ B,
             __nv_bfloat16* __restrict__ whTg, int K,
             const float* __restrict__ av1, const float* __restrict__ av2,
             float* __restrict__ s1, float* __restrict__ e2,
             float* __restrict__ e2b, unsigned* __restrict__ gmaxi) {
    __shared__ __nv_bfloat16 As[2][128 * 40];
    __shared__ __nv_bfloat16 Bs[2][64 * 40];
    __shared__ float a1s[64], a2s[64];

    const int t  = threadIdx.x;
    const int m0 = blockIdx.y * 128;
    const int n0 = blockIdx.x * 64;
    const int w = t >> 5, ln = t & 31;
    const int r = ln >> 2, c = ln & 3;

    if (t < 64)       a1s[t]      = av1[n0 + t] * LOG2E;
    else if (t < 128) a2s[t - 64] = av2[n0 + t - 64] * LOG2E;

    const uint32_t aB = sptr(As[0]) + (uint32_t)(((w * 16 + (ln & 15)) * 40 +
                                                  ((ln >> 4) & 1) * 8) * 2);
    const uint32_t bB = sptr(Bs[0]) + (uint32_t)((((ln & 7) + ((ln >> 4) & 1) * 8) * 40 +
                                                  ((ln >> 3) & 1) * 8) * 2);
    const uint32_t ABUF = 128 * 40 * 2;
    const uint32_t BBUF = 64 * 40 * 2;

    float acc[8][4];
#pragma unroll
    for (int nt = 0; nt < 8; ++nt)
#pragma unroll
        for (int q = 0; q < 4; ++q) acc[nt][q] = 0.f;

    auto g_issue = [&](int ki) {
        int buf = ki & 1;
        int kc = ki * 32;
#pragma unroll
        for (int it = 0; it < 2; ++it) {
            int idx = it * 256 + t;
            int row = idx >> 2, u = idx & 3;
            cpa16(sptr(&As[buf][row * 40 + u * 8]),
                  A + (size_t)(m0 + row) * K + kc + u * 8);
        }
        {
            int row = t >> 2, u = t & 3;
            cpa16(sptr(&Bs[buf][row * 40 + u * 8]),
                  B + (size_t)(n0 + row) * K + kc + u * 8);
        }
    };

    const int NK = K / 32;
    g_issue(0); cpa_commit();
    for (int ki = 0; ki < NK; ++ki) {
        if (ki + 1 < NK) { g_issue(ki + 1); cpa_commit(); cpa_wait<1>(); }
        else             { cpa_wait<0>(); }
        __syncthreads();
        const int buf = ki & 1;
#pragma unroll
        for (int kt = 0; kt < 2; ++kt) {
            uint32_t a[4];
            ldsm4(a, aB + buf * ABUF + kt * 32);
#pragma unroll
            for (int p = 0; p < 4; ++p) {
                uint32_t b[4];
                ldsm4(b, bB + buf * BBUF + p * 1280 + kt * 32);
                mma16816(acc[2 * p],     a, b[0], b[1]);
                mma16816(acc[2 * p + 1], a, b[2], b[3]);
            }
        }
        __syncthreads();
    }

    // ---- fused scores ----
    const int rA = m0 + w * 16 + r;
    float p1A = 0.f, p2A = 0.f, p1B = 0.f, p2B = 0.f;
#pragma unroll
    for (int nt = 0; nt < 8; ++nt) {
        float x1a = a1s[nt * 8 + c * 2], x1b = a1s[nt * 8 + c * 2 + 1];
        float x2a = a2s[nt * 8 + c * 2], x2b = a2s[nt * 8 + c * 2 + 1];
        p1A += acc[nt][0] * x1a + acc[nt][1] * x1b;
        p2A += acc[nt][0] * x2a + acc[nt][1] * x2b;
        p1B += acc[nt][2] * x1a + acc[nt][3] * x1b;
        p2B += acc[nt][2] * x2a + acc[nt][3] * x2b;
    }
#pragma unroll
    for (int o = 2; o; o >>= 1) {
        p1A += __shfl_down_sync(0xffffffffu, p1A, o);
        p2A += __shfl_down_sync(0xffffffffu, p2A, o);
        p1B += __shfl_down_sync(0xffffffffu, p1B, o);
        p2B += __shfl_down_sync(0xffffffffu, p2B, o);
    }
    if (c == 0) {
        int h = n0 >> 6;
        s1[h * GN + rA]      = p1A;
        e2[h * GN + rA]      = ex2f(p2A);
        e2b[h * GN + rA]     = ex2f(0.2f * p2A);
        s1[h * GN + rA + 8]  = p1B;
        e2[h * GN + rA + 8]  = ex2f(p2B);
        e2b[h * GN + rA + 8] = ex2f(0.2f * p2B);
        atomicMax(&gmaxi[h], fenc(fmaxf(p2A, p2B)));
    }

    // ---- fused transposed bf16 output via smem staging (reuse As) ----
    __nv_bfloat16* Ts = As[0];
    {
        int rl = w * 16 + r;
#pragma unroll
        for (int nt = 0; nt < 8; ++nt) {
            int cc = nt * 8 + c * 2;
            Ts[cc * 136 + rl]           = __float2bfloat16(acc[nt][0]);
            Ts[(cc + 1) * 136 + rl]     = __float2bfloat16(acc[nt][1]);
            Ts[cc * 136 + rl + 8]       = __float2bfloat16(acc[nt][2]);
            Ts[(cc + 1) * 136 + rl + 8] = __float2bfloat16(acc[nt][3]);
        }
    }
    __syncthreads();
#pragma unroll
    for (int it = 0; it < 4; ++it) {
        int idx = it * 256 + t;
        int col = idx >> 4, u = idx & 15;
        uint4 v = *(const uint4*)(Ts + col * 136 + u * 8);
        *(uint4*)(whTg + (size_t)(n0 + col) * GN + m0 + u * 8) = v;
    }
}

// ---------------- fused masked softmax + att@wh, in-register A fragments --
// Lane (r,c) of warp w computes exactly its mma A-fragment words:
// P[16w+r(+8)][kt*16 + hb*8 + 2c(+1)] = max(E2[j]*ci_row, E2b[j]*ci2_row)
// masked by adj. No P smem array, no A ldsm, no phase barrier. E2/E2b tables
// preloaded for the block's whole j-range.
template<int JS>
__global__ void __launch_bounds__(256, 3)
attn_mma_kernel(const __nv_bfloat16* __restrict__ whT,
                const float* __restrict__ s1g,
                const float* __restrict__ e2g, const float* __restrict__ e2bg,
                const unsigned* __restrict__ gmaxi,
                const uint32_t* __restrict__ adjbits,
                float* __restrict__ part) {
    constexpr int NJ = GN / JS;
    constexpr int NT = NJ / 64;
    __shared__ __nv_bfloat16 whs[2][72 * 72];
    __shared__ float e2s[NJ];
    __shared__ float e2bs[NJ];

    const int t  = threadIdx.x;
    const int i0 = blockIdx.x * 128;
    const int h  = blockIdx.y;
    const int jbase = blockIdx.z * NJ;

    const __nv_bfloat16* whTh = whT + (size_t)h * 64 * GN;

    // constant rows 64..71 of both whs buffers (row 64 = ones -> den column)
#pragma unroll
    for (int b = 0; b < 2; ++b)
        for (int idx = t; idx < 8 * 36; idx += 256) {
            int rr = idx / 36, wd = idx - rr * 36;
            reinterpret_cast<uint32_t*>(whs[b])[(64 + rr) * 36 + wd] =
                (rr == 0) ? 0x3F803F80u : 0u;
        }

    auto issue_tile = [&](int tt) {
        int buf = tt & 1;
        int j0 = jbase + tt * 64;
#pragma unroll
        for (int it = 0; it < 2; ++it) {
            int idx = it * 256 + t;
            int f = idx >> 3, u = idx & 7;
            cpa16(sptr(&whs[buf][f * 72 + u * 8]), whTh + (size_t)f * GN + j0 + u * 8);
        }
    };

    // preload E2/E2b for the whole j-range + first wh tile (one group)
    {
        const float* e2h  = e2g  + h * GN + jbase;
        const float* e2bh = e2bg + h * GN + jbase;
        for (int idx = t * 4; idx < NJ; idx += 1024) {
            cpa16(sptr(&e2s[idx]),  e2h  + idx);
            cpa16(sptr(&e2bs[idx]), e2bh + idx);
        }
    }
    issue_tile(0);
    cpa_commit();

    const int w = t >> 5, ln = t & 31;
    const int r = ln >> 2, c = ln & 3;
    const int lr0 = w * 16 + r;                    // block-local rows
    const int lr1 = lr0 + 8;

    // per-row softmax constants for this lane's two rows
    const float s1a = s1g[h * GN + i0 + lr0];
    const float s1b = s1g[h * GN + i0 + lr1];
    const float gmx = fdec(gmaxi[h]);
    const float ma  = fmaxf(s1a + gmx, 0.2f * (s1a + gmx));
    const float mb  = fmaxf(s1b + gmx, 0.2f * (s1b + gmx));
    const float ci0  = ex2f(s1a - ma),        ci1  = ex2f(s1b - mb);
    const float ci20 = ex2f(0.2f * s1a - ma), ci21 = ex2f(0.2f * s1b - mb);

    const uint32_t whB0 = sptr(whs[0]) + (uint32_t)((((ln & 7) + ((ln >> 4) & 1) * 8) * 72 +
                                                     ((ln >> 3) & 1) * 8) * 2);
    const uint32_t dnB0 = sptr(whs[0]) + (uint32_t)(((64 + (ln & 7)) * 72 +
                                                     ((ln >> 3) & 1) * 8) * 2);
    const uint32_t bufStride = (uint32_t)(72 * 72 * 2);

    const uint32_t* adjRow0 = adjbits + (size_t)(i0 + lr0) * ADJW + (jbase >> 5);
    const uint32_t* adjRow1 = adjbits + (size_t)(i0 + lr1) * ADJW + (jbase >> 5);
    const float2* e2s2  = reinterpret_cast<const float2*>(e2s);
    const float2* e2bs2 = reinterpret_cast<const float2*>(e2bs);

    float acc[9][4];
#pragma unroll
    for (int nt = 0; nt < 9; ++nt)
#pragma unroll
        for (int q = 0; q < 4; ++q) acc[nt][q] = 0.f;

    for (int tt = 0; tt < NT; ++tt) {
        cpa_wait<0>();           // wh(tt) (+tables on tt=0) done
        __syncthreads();         // visible; phase2(tt-1) done (whs WAR safe)
        if (tt + 1 < NT) { issue_tile(tt + 1); cpa_commit(); }

        // ---- phase 1: A fragments in registers, no smem round-trip ----
        const uint2 aw0 = *(const uint2*)(adjRow0 + tt * 2);
        const uint2 aw1 = *(const uint2*)(adjRow1 + tt * 2);
        uint32_t a[4][4];
#pragma unroll
        for (int kt = 0; kt < 4; ++kt) {
#pragma unroll
            for (int hb = 0; hb < 2; ++hb) {
                const int jj = kt * 16 + hb * 8 + 2 * c;
                const float2 ev = e2s2[tt * 32 + kt * 8 + hb * 4 + c];
                const float2 bv = e2bs2[tt * 32 + kt * 8 + hb * 4 + c];
                const uint32_t w0 = (jj < 32) ? aw0.x : aw0.y;
                const uint32_t w1 = (jj < 32) ? aw1.x : aw1.y;
                const int b = jj & 31;
                float q00 = fmaxf(ev.x * ci0, bv.x * ci20);
                float q01 = fmaxf(ev.y * ci0, bv.y * ci20);
                float q10 = fmaxf(ev.x * ci1, bv.x * ci21);
                float q11 = fmaxf(ev.y * ci1, bv.y * ci21);
                q00 = ((w0 >> b) & 1u)       ? q00 : 0.f;
                q01 = ((w0 >> (b + 1)) & 1u) ? q01 : 0.f;
                q10 = ((w1 >> b) & 1u)       ? q10 : 0.f;
                q11 = ((w1 >> (b + 1)) & 1u) ? q11 : 0.f;
                __nv_bfloat162 h0 = __floats2bfloat162_rn(q00, q01);
                __nv_bfloat162 h1 = __floats2bfloat162_rn(q10, q11);
                a[kt][hb * 2]     = *reinterpret_cast<uint32_t*>(&h0);
                a[kt][hb * 2 + 1] = *reinterpret_cast<uint32_t*>(&h1);
            }
        }

        // ---- phase 2: B ldsm + mma (A already in registers) ----
        const int buf = tt & 1;
        const uint32_t whB = whB0 + buf * bufStride;
        const uint32_t dnB = dnB0 + buf * bufStride;
#pragma unroll
        for (int kt = 0; kt < 4; ++kt) {
#pragma unroll
            for (int p = 0; p < 4; ++p) {
                uint32_t b[4];
                ldsm4(b, whB + p * 2304 + kt * 32);
                mma16816(acc[2 * p],     a[kt], b[0], b[1]);
                mma16816(acc[2 * p + 1], a[kt], b[2], b[3]);
            }
            uint32_t d[2];
            ldsm2(d, dnB + kt * 32);
            mma16816(acc[8], a[kt], d[0], d[1]);
        }
    }

    // ---- store partials: slot = h*JS + z ----
    int rA = i0 + lr0;
    float* pA = part + (((size_t)(h * JS + blockIdx.z)) * GN + rA) * 72;
    float* pB = pA + 8 * 72;
#pragma unroll
    for (int nt = 0; nt < 8; ++nt) {
        int col = nt * 8 + c * 2;
        *(float2*)(pA + col) = make_float2(acc[nt][0], acc[nt][1]);
        *(float2*)(pB + col) = make_float2(acc[nt][2], acc[nt][3]);
    }
    if (c == 0) { pA[64] = acc[8][0]; pB[64] = acc[8][2]; }
}

// ---------------- layer-1 reduce: sum JS1 partials, ELU, bf16 store --------
__global__ void reduce_hbuf_kernel(const float* __restrict__ part,
                                   __nv_bfloat16* __restrict__ outB) {
    int id  = blockIdx.x * 256 + threadIdx.x;
    int row = id >> 8;
    int cp  = (id & 255) * 2;
    int h   = cp >> 6;
    int cl  = cp & 63;
    float n0 = 0.f, n1 = 0.f, d = 0.f;
#pragma unroll
    for (int js = 0; js < JS1; ++js) {
        const float* rp = part + (((size_t)(h * JS1 + js)) * GN + row) * 72;
        float2 nv = *(const float2*)(rp + cl);
        n0 += nv.x; n1 += nv.y; d += rp[64];
    }
    float inv = 1.f / d;
    float v0 = n0 * inv;
    float v1 = n1 * inv;
    v0 = v0 > 0.f ? v0 : (ex2f(v0 * LOG2E) - 1.f);
    v1 = v1 > 0.f ? v1 : (ex2f(v1 * LOG2E) - 1.f);
    *(__nv_bfloat162*)(outB + (size_t)row * FCAT + cp) = __floats2bfloat162_rn(v0, v1);
}

// ---------------- layer-2 reduce: sum JS2 partials + ELU + log_softmax ----
__global__ void reduce_lsm_kernel(const float* __restrict__ part,
                                  float* __restrict__ out) {
    int row = blockIdx.x * 8 + (threadIdx.x >> 5);
    int ln  = threadIdx.x & 31;
    float n0 = 0.f, n1 = 0.f, d = 0.f;
#pragma unroll
    for (int js = 0; js < JS2; ++js) {
        const float* b = part + ((size_t)js * GN + row) * 72;
        n0 += b[ln]; n1 += b[ln + 32]; d += b[64];
    }
    float inv = 1.f / d;
    float v0 = n0 * inv, v1 = n1 * inv;
    v0 = v0 > 0.f ? v0 : (__expf(v0) - 1.f);
    v1 = v1 > 0.f ? v1 : (__expf(v1) - 1.f);
    float mx = fmaxf(v0, v1);
#pragma unroll
    for (int o = 16; o; o >>= 1) mx = fmaxf(mx, __shfl_xor_sync(0xffffffffu, mx, o));
    float s = __expf(v0 - mx) + __expf(v1 - mx);
#pragma unroll
    for (int o = 16; o; o >>= 1) s += __shfl_xor_sync(0xffffffffu, s, o);
    float l = mx + __logf(s);
    out[(size_t)row * 64 + ln]      = v0 - l;
    out[(size_t)row * 64 + ln + 32] = v1 - l;
}

// ---------------- launch ----------------
extern "C" void kernel_launch(void* const* d_in, const int* in_sizes, int n_in,
                              void* d_out, int out_size) {
    const float* x   = (const float*)d_in[0];
    const int*   adj = (const int*)d_in[1];
    const float* W   = (const float*)d_in[2];
    const float* a1  = (const float*)d_in[3];
    const float* a2  = (const float*)d_in[4];
    const float* W2  = (const float*)d_in[5];
    const float* a21 = (const float*)d_in[6];
    const float* a22 = (const float*)d_in[7];
    float* out = (float*)d_out;

    uint32_t* adjbits; unsigned* gmaxi;
    float *s1, *e2, *e2b, *s21, *e22, *e22b, *part;
    __nv_bfloat16 *xb, *Wb, *W2b, *whTb, *hbufb, *whT2b;
    cudaGetSymbolAddress((void**)&adjbits, g_adjbits);
    cudaGetSymbolAddress((void**)&gmaxi, g_gmaxi);
    cudaGetSymbolAddress((void**)&xb,    g_xb);
    cudaGetSymbolAddress((void**)&Wb,    g_Wb);
    cudaGetSymbolAddress((void**)&W2b,   g_W2b);
    cudaGetSymbolAddress((void**)&whTb,  g_whTb);
    cudaGetSymbolAddress((void**)&s1,    g_s1);
    cudaGetSymbolAddress((void**)&e2,    g_e2);
    cudaGetSymbolAddress((void**)&e2b,   g_e2b);
    cudaGetSymbolAddress((void**)&hbufb, g_hbufb);
    cudaGetSymbolAddress((void**)&whT2b, g_whT2b);
    cudaGetSymbolAddress((void**)&s21,   g_s21);
    cudaGetSymbolAddress((void**)&e22,   g_e22);
    cudaGetSymbolAddress((void**)&e22b,  g_e22b);
    cudaGetSymbolAddress((void**)&part,  g_part);

    pack_adj_kernel<<<(GN * GN) / 1024, 256>>>(adj, adjbits, gmaxi);
    cvt_all_kernel<<<(GN * FCAT + FCAT * FCAT + HIDF * FCAT) / 512, 256>>>(
        x, xb, W, Wb, W2, W2b);
    gemm_bf16_nt<<<dim3(FCAT / 64, GN / 128), 256>>>(xb, Wb, whTb, FCAT,
                                                     a1, a2, s1, e2, e2b, gmaxi);
    attn_mma_kernel<JS1><<<dim3(GN / 128, GH, JS1), 256>>>(whTb, s1, e2, e2b,
                                                           gmaxi, adjbits, part);
    reduce_hbuf_kernel<<<GN, 256>>>(part, hbufb);
    gemm_bf16_nt<<<dim3(1, GN / 128), 256>>>(hbufb, W2b, whT2b, FCAT,
                                             a21, a22, s21, e22, e22b, gmaxi + 8);
    attn_mma_kernel<JS2><<<dim3(GN / 128, 1, JS2), 256>>>(whT2b, s21, e22, e22b,
                                                          gmaxi + 8, adjbits, part);
    reduce_lsm_kernel<<<GN / 8, 256>>>(part, out);
}

// round 17
// speedup vs baseline: 1.3611x; 1.0281x over previous
#include <cuda_runtime.h>
#include <cuda_bf16.h>
#include <stdint.h>

#define GN 4096
#define GH 8
#define FCAT 512
#define HIDF 64
#define ADJW (GN/32)
#define JS1 4
#define JS2 16
#define LOG2E 1.4426950408889634f

// ---------------- scratch ----------------
__device__ uint32_t      g_adjbits[GN * ADJW];
__device__ __nv_bfloat16 g_xb[GN * FCAT];
__device__ __nv_bfloat16 g_Wb[FCAT * FCAT];
__device__ __nv_bfloat16 g_W2b[HIDF * FCAT];
__device__ __nv_bfloat16 g_whTb[FCAT * GN];
__device__ float         g_s1[GH * GN];
__device__ float         g_e2[GH * GN];
__device__ float         g_e2b[GH * GN];
__device__ unsigned      g_gmaxi[16];
__device__ __nv_bfloat16 g_hbufb[GN * FCAT];
__device__ __nv_bfloat16 g_whT2b[HIDF * GN];
__device__ float         g_s21[GN];
__device__ float         g_e22[GN];
__device__ float         g_e22b[GN];
__device__ float         g_part[32 * GN * 72];

__device__ __forceinline__ unsigned fenc(float f) {
    unsigned b = __float_as_uint(f);
    return (b & 0x80000000u) ? ~b : (b | 0x80000000u);
}
__device__ __forceinline__ float fdec(unsigned k) {
    return __uint_as_float((k & 0x80000000u) ? (k & 0x7fffffffu) : ~k);
}
__device__ __forceinline__ float ex2f(float x) {
    float y; asm("ex2.approx.f32 %0, %1;" : "=f"(y) : "f"(x)); return y;
}
__device__ __forceinline__ uint32_t sptr(const void* p) {
    return (uint32_t)__cvta_generic_to_shared(p);
}
__device__ __forceinline__ void ldsm4(uint32_t* r, uint32_t a) {
    asm volatile("ldmatrix.sync.aligned.m8n8.x4.shared.b16 {%0,%1,%2,%3}, [%4];"
                 : "=r"(r[0]), "=r"(r[1]), "=r"(r[2]), "=r"(r[3]) : "r"(a));
}
__device__ __forceinline__ void ldsm2(uint32_t* r, uint32_t a) {
    asm volatile("ldmatrix.sync.aligned.m8n8.x2.shared.b16 {%0,%1}, [%2];"
                 : "=r"(r[0]), "=r"(r[1]) : "r"(a));
}
__device__ __forceinline__ void cpa16(uint32_t dst, const void* src) {
    asm volatile("cp.async.cg.shared.global [%0], [%1], 16;" :: "r"(dst), "l"(src));
}
__device__ __forceinline__ void cpa_commit() {
    asm volatile("cp.async.commit_group;");
}
template<int N>
__device__ __forceinline__ void cpa_wait() {
    asm volatile("cp.async.wait_group %0;" :: "n"(N));
}
__device__ __forceinline__ void mma16816(float* d, const uint32_t* a,
                                         uint32_t b0, uint32_t b1) {
    asm volatile(
        "mma.sync.aligned.m16n8k16.row.col.f32.bf16.bf16.f32 "
        "{%0,%1,%2,%3}, {%4,%5,%6,%7}, {%8,%9}, {%0,%1,%2,%3};"
        : "+f"(d[0]), "+f"(d[1]), "+f"(d[2]), "+f"(d[3])
        : "r"(a[0]), "r"(a[1]), "r"(a[2]), "r"(a[3]), "r"(b0), "r"(b1));
}

// ---------------- pack adjacency (4x unrolled) + init gmax ----------------
__global__ void pack_adj_kernel(const int* __restrict__ adj,
                                uint32_t* __restrict__ bits,
                                unsigned* __restrict__ gmaxi) {
    if (blockIdx.x == 0 && threadIdx.x < 16) gmaxi[threadIdx.x] = 0u;
    int wg   = (blockIdx.x * 256 + threadIdx.x) >> 5;
    int lane = threadIdx.x & 31;
    int base = wg * 128;
    int v0 = adj[base + lane];
    int v1 = adj[base + 32 + lane];
    int v2 = adj[base + 64 + lane];
    int v3 = adj[base + 96 + lane];
    uint32_t b[4];
    b[0] = __ballot_sync(0xffffffffu, v0 > 0);
    b[1] = __ballot_sync(0xffffffffu, v1 > 0);
    b[2] = __ballot_sync(0xffffffffu, v2 > 0);
    b[3] = __ballot_sync(0xffffffffu, v3 > 0);
    if (lane < 4) bits[wg * 4 + lane] = b[lane];
}

// ---------------- fp32 -> bf16, all three inputs in one launch ------------
__global__ void cvt_all_kernel(const float* __restrict__ x, __nv_bfloat16* __restrict__ xb,
                               const float* __restrict__ W, __nv_bfloat16* __restrict__ Wb,
                               const float* __restrict__ W2, __nv_bfloat16* __restrict__ W2b) {
    const int NX = GN * FCAT / 2, NW = FCAT * FCAT / 2;
    int id = blockIdx.x * 256 + threadIdx.x;
    const float* src; __nv_bfloat16* dst; int off;
    if (id < NX)           { src = x;  dst = xb;  off = id; }
    else if (id < NX + NW) { src = W;  dst = Wb;  off = id - NX; }
    else                   { src = W2; dst = W2b; off = id - NX - NW; }
    float2 v = *(const float2*)(src + (size_t)off * 2);
    *(__nv_bfloat162*)(dst + (size_t)off * 2) = __floats2bfloat162_rn(v.x, v.y);
}

// ---------------- bf16 NT GEMM + fused scores + fused transposed output ---
__global__ void __launch_bounds__(256, 3)
gemm_bf16_nt(const __nv_bfloat16* __restrict__ A,
             const __nv_bfloat16* __restrict__ B,
             __nv_bfloat16* __restrict__ whTg, int K,
             const float* __restrict__ av1, const float* __restrict__ av2,
             float* __restrict__ s1, float* __restrict__ e2,
             float* __restrict__ e2b, unsigned* __restrict__ gmaxi) {
    __shared__ __nv_bfloat16 As[2][128 * 40];
    __shared__ __nv_bfloat16 Bs[2][64 * 40];
    __shared__ float a1s[64], a2s[64];

    const int t  = threadIdx.x;
    const int m0 = blockIdx.y * 128;
    const int n0 = blockIdx.x * 64;
    const int w = t >> 5, ln = t & 31;
    const int r = ln >> 2, c = ln & 3;

    if (t < 64)       a1s[t]      = av1[n0 + t] * LOG2E;
    else if (t < 128) a2s[t - 64] = av2[n0 + t - 64] * LOG2E;

    const uint32_t aB = sptr(As[0]) + (uint32_t)(((w * 16 + (ln & 15)) * 40 +
                                                  ((ln >> 4) & 1) * 8) * 2);
    const uint32_t bB = sptr(Bs[0]) + (uint32_t)((((ln & 7) + ((ln >> 4) & 1) * 8) * 40 +
                                                  ((ln >> 3) & 1) * 8) * 2);
    const uint32_t ABUF = 128 * 40 * 2;
    const uint32_t BBUF = 64 * 40 * 2;

    float acc[8][4];
#pragma unroll
    for (int nt = 0; nt < 8; ++nt)
#pragma unroll
        for (int q = 0; q < 4; ++q) acc[nt][q] = 0.f;

    auto g_issue = [&](int ki) {
        int buf = ki & 1;
        int kc = ki * 32;
#pragma unroll
        for (int it = 0; it < 2; ++it) {
            int idx = it * 256 + t;
            int row = idx >> 2, u = idx & 3;
            cpa16(sptr(&As[buf][row * 40 + u * 8]),
                  A + (size_t)(m0 + row) * K + kc + u * 8);
        }
        {
            int row = t >> 2, u = t & 3;
            cpa16(sptr(&Bs[buf][row * 40 + u * 8]),
                  B + (size_t)(n0 + row) * K + kc + u * 8);
        }
    };

    const int NK = K / 32;
    g_issue(0); cpa_commit();
    for (int ki = 0; ki < NK; ++ki) {
        if (ki + 1 < NK) { g_issue(ki + 1); cpa_commit(); cpa_wait<1>(); }
        else             { cpa_wait<0>(); }
        __syncthreads();
        const int buf = ki & 1;
#pragma unroll
        for (int kt = 0; kt < 2; ++kt) {
            uint32_t a[4];
            ldsm4(a, aB + buf * ABUF + kt * 32);
#pragma unroll
            for (int p = 0; p < 4; ++p) {
                uint32_t b[4];
                ldsm4(b, bB + buf * BBUF + p * 1280 + kt * 32);
                mma16816(acc[2 * p],     a, b[0], b[1]);
                mma16816(acc[2 * p + 1], a, b[2], b[3]);
            }
        }
        __syncthreads();
    }

    // ---- fused scores ----
    const int rA = m0 + w * 16 + r;
    float p1A = 0.f, p2A = 0.f, p1B = 0.f, p2B = 0.f;
#pragma unroll
    for (int nt = 0; nt < 8; ++nt) {
        float x1a = a1s[nt * 8 + c * 2], x1b = a1s[nt * 8 + c * 2 + 1];
        float x2a = a2s[nt * 8 + c * 2], x2b = a2s[nt * 8 + c * 2 + 1];
        p1A += acc[nt][0] * x1a + acc[nt][1] * x1b;
        p2A += acc[nt][0] * x2a + acc[nt][1] * x2b;
        p1B += acc[nt][2] * x1a + acc[nt][3] * x1b;
        p2B += acc[nt][2] * x2a + acc[nt][3] * x2b;
    }
#pragma unroll
    for (int o = 2; o; o >>= 1) {
        p1A += __shfl_down_sync(0xffffffffu, p1A, o);
        p2A += __shfl_down_sync(0xffffffffu, p2A, o);
        p1B += __shfl_down_sync(0xffffffffu, p1B, o);
        p2B += __shfl_down_sync(0xffffffffu, p2B, o);
    }
    if (c == 0) {
        int h = n0 >> 6;
        s1[h * GN + rA]      = p1A;
        e2[h * GN + rA]      = ex2f(p2A);
        e2b[h * GN + rA]     = ex2f(0.2f * p2A);
        s1[h * GN + rA + 8]  = p1B;
        e2[h * GN + rA + 8]  = ex2f(p2B);
        e2b[h * GN + rA + 8] = ex2f(0.2f * p2B);
        atomicMax(&gmaxi[h], fenc(fmaxf(p2A, p2B)));
    }

    // ---- fused transposed bf16 output via smem staging (reuse As) ----
    __nv_bfloat16* Ts = As[0];
    {
        int rl = w * 16 + r;
#pragma unroll
        for (int nt = 0; nt < 8; ++nt) {
            int cc = nt * 8 + c * 2;
            Ts[cc * 136 + rl]           = __float2bfloat16(acc[nt][0]);
            Ts[(cc + 1) * 136 + rl]     = __float2bfloat16(acc[nt][1]);
            Ts[cc * 136 + rl + 8]       = __float2bfloat16(acc[nt][2]);
            Ts[(cc + 1) * 136 + rl + 8] = __float2bfloat16(acc[nt][3]);
        }
    }
    __syncthreads();
#pragma unroll
    for (int it = 0; it < 4; ++it) {
        int idx = it * 256 + t;
        int col = idx >> 4, u = idx & 15;
        uint4 v = *(const uint4*)(Ts + col * 136 + u * 8);
        *(uint4*)(whTg + (size_t)(n0 + col) * GN + m0 + u * 8) = v;
    }
}

// ---------------- fused masked softmax + att@wh, 2 m-tiles per warp -------
// 128 threads / 4 warps; warp w owns rows [32w, 32w+32) = m-tiles {0,1}.
// Each B fragment (and table read) now serves BOTH m-tiles -> B ldsm traffic
// halves vs 8-warp layout. A fragments built per-kt in registers (no P smem).
template<int JS>
__global__ void __launch_bounds__(128, 4)
attn_mma_kernel(const __nv_bfloat16* __restrict__ whT,
                const float* __restrict__ s1g,
                const float* __restrict__ e2g, const float* __restrict__ e2bg,
                const unsigned* __restrict__ gmaxi,
                const uint32_t* __restrict__ adjbits,
                float* __restrict__ part) {
    constexpr int NJ = GN / JS;
    constexpr int NT = NJ / 64;
    __shared__ __nv_bfloat16 whs[2][72 * 72];
    __shared__ float e2s[NJ];
    __shared__ float e2bs[NJ];

    const int t  = threadIdx.x;
    const int i0 = blockIdx.x * 128;
    const int h  = blockIdx.y;
    const int jbase = blockIdx.z * NJ;

    const __nv_bfloat16* whTh = whT + (size_t)h * 64 * GN;

    // constant rows 64..71 of both whs buffers (row 64 = ones -> den column)
#pragma unroll
    for (int b = 0; b < 2; ++b)
        for (int idx = t; idx < 8 * 36; idx += 128) {
            int rr = idx / 36, wd = idx - rr * 36;
            reinterpret_cast<uint32_t*>(whs[b])[(64 + rr) * 36 + wd] =
                (rr == 0) ? 0x3F803F80u : 0u;
        }

    auto issue_tile = [&](int tt) {
        int buf = tt & 1;
        int j0 = jbase + tt * 64;
#pragma unroll
        for (int it = 0; it < 4; ++it) {
            int idx = it * 128 + t;
            int f = idx >> 3, u = idx & 7;
            cpa16(sptr(&whs[buf][f * 72 + u * 8]), whTh + (size_t)f * GN + j0 + u * 8);
        }
    };

    // preload E2/E2b for the whole j-range + first wh tile (one group)
    {
        const float* e2h  = e2g  + h * GN + jbase;
        const float* e2bh = e2bg + h * GN + jbase;
        for (int idx = t * 4; idx < NJ; idx += 512) {
            cpa16(sptr(&e2s[idx]),  e2h  + idx);
            cpa16(sptr(&e2bs[idx]), e2bh + idx);
        }
    }
    issue_tile(0);
    cpa_commit();

    const int w = t >> 5, ln = t & 31;
    const int r = ln >> 2, c = ln & 3;
    const int lr0 = w * 32 + r;                    // rows: lr0, +8, +16, +24

    // per-row softmax constants for this lane's 4 rows
    const float gmx = fdec(gmaxi[h]);
    float ci[4], ci2[4];
#pragma unroll
    for (int q = 0; q < 4; ++q) {
        float s1v = s1g[h * GN + i0 + lr0 + q * 8];
        float mm  = fmaxf(s1v + gmx, 0.2f * (s1v + gmx));
        ci[q]  = ex2f(s1v - mm);
        ci2[q] = ex2f(0.2f * s1v - mm);
    }

    const uint32_t whB0 = sptr(whs[0]) + (uint32_t)((((ln & 7) + ((ln >> 4) & 1) * 8) * 72 +
                                                     ((ln >> 3) & 1) * 8) * 2);
    const uint32_t dnB0 = sptr(whs[0]) + (uint32_t)(((64 + (ln & 7)) * 72 +
                                                     ((ln >> 3) & 1) * 8) * 2);
    const uint32_t bufStride = (uint32_t)(72 * 72 * 2);

    const uint32_t* adjR[4];
#pragma unroll
    for (int q = 0; q < 4; ++q)
        adjR[q] = adjbits + (size_t)(i0 + lr0 + q * 8) * ADJW + (jbase >> 5);
    const float2* e2s2  = reinterpret_cast<const float2*>(e2s);
    const float2* e2bs2 = reinterpret_cast<const float2*>(e2bs);

    float acc[2][9][4];
#pragma unroll
    for (int mt = 0; mt < 2; ++mt)
#pragma unroll
        for (int nt = 0; nt < 9; ++nt)
#pragma unroll
            for (int q = 0; q < 4; ++q) acc[mt][nt][q] = 0.f;

    for (int tt = 0; tt < NT; ++tt) {
        cpa_wait<0>();
        __syncthreads();
        if (tt + 1 < NT) { issue_tile(tt + 1); cpa_commit(); }

        uint2 aw[4];
#pragma unroll
        for (int q = 0; q < 4; ++q) aw[q] = *(const uint2*)(adjR[q] + tt * 2);

        const int buf = tt & 1;
        const uint32_t whB = whB0 + buf * bufStride;
        const uint32_t dnB = dnB0 + buf * bufStride;

#pragma unroll
        for (int kt = 0; kt < 4; ++kt) {
            // ---- build A fragments for both m-tiles (registers only) ----
            uint32_t a0[4], a1[4];
#pragma unroll
            for (int hb = 0; hb < 2; ++hb) {
                const int jj = kt * 16 + hb * 8 + 2 * c;
                const float2 ev = e2s2[tt * 32 + kt * 8 + hb * 4 + c];
                const float2 bv = e2bs2[tt * 32 + kt * 8 + hb * 4 + c];
                const int b = jj & 31;
#pragma unroll
                for (int mt = 0; mt < 2; ++mt) {
#pragma unroll
                    for (int rr = 0; rr < 2; ++rr) {
                        const int q = mt * 2 + rr;
                        const uint32_t wv = (jj < 32) ? aw[q].x : aw[q].y;
                        float qa = fmaxf(ev.x * ci[q], bv.x * ci2[q]);
                        float qb = fmaxf(ev.y * ci[q], bv.y * ci2[q]);
                        qa = ((wv >> b) & 1u)       ? qa : 0.f;
                        qb = ((wv >> (b + 1)) & 1u) ? qb : 0.f;
                        __nv_bfloat162 hq = __floats2bfloat162_rn(qa, qb);
                        uint32_t word = *reinterpret_cast<uint32_t*>(&hq);
                        if (mt == 0) a0[hb * 2 + rr] = word;
                        else         a1[hb * 2 + rr] = word;
                    }
                }
            }
            // ---- B ldsm once, mma both m-tiles ----
#pragma unroll
            for (int p = 0; p < 4; ++p) {
                uint32_t b[4];
                ldsm4(b, whB + p * 2304 + kt * 32);
                mma16816(acc[0][2 * p],     a0, b[0], b[1]);
                mma16816(acc[0][2 * p + 1], a0, b[2], b[3]);
                mma16816(acc[1][2 * p],     a1, b[0], b[1]);
                mma16816(acc[1][2 * p + 1], a1, b[2], b[3]);
            }
            uint32_t d[2];
            ldsm2(d, dnB + kt * 32);
            mma16816(acc[0][8], a0, d[0], d[1]);
            mma16816(acc[1][8], a1, d[0], d[1]);
        }
    }

    // ---- store partials: slot = h*JS + z ----
#pragma unroll
    for (int mt = 0; mt < 2; ++mt) {
        int rA = i0 + w * 32 + mt * 16 + r;
        float* pA = part + (((size_t)(h * JS + blockIdx.z)) * GN + rA) * 72;
        float* pB = pA + 8 * 72;
#pragma unroll
        for (int nt = 0; nt < 8; ++nt) {
            int col = nt * 8 + c * 2;
            *(float2*)(pA + col) = make_float2(acc[mt][nt][0], acc[mt][nt][1]);
            *(float2*)(pB + col) = make_float2(acc[mt][nt][2], acc[mt][nt][3]);
        }
        if (c == 0) { pA[64] = acc[mt][8][0]; pB[64] = acc[mt][8][2]; }
    }
}

// ---------------- layer-1 reduce: sum JS1 partials, ELU, bf16 store --------
__global__ void reduce_hbuf_kernel(const float* __restrict__ part,
                                   __nv_bfloat16* __restrict__ outB) {
    int id  = blockIdx.x * 256 + threadIdx.x;
    int row = id >> 8;
    int cp  = (id & 255) * 2;
    int h   = cp >> 6;
    int cl  = cp & 63;
    float n0 = 0.f, n1 = 0.f, d = 0.f;
#pragma unroll
    for (int js = 0; js < JS1; ++js) {
        const float* rp = part + (((size_t)(h * JS1 + js)) * GN + row) * 72;
        float2 nv = *(const float2*)(rp + cl);
        n0 += nv.x; n1 += nv.y; d += rp[64];
    }
    float inv = 1.f / d;
    float v0 = n0 * inv;
    float v1 = n1 * inv;
    v0 = v0 > 0.f ? v0 : (ex2f(v0 * LOG2E) - 1.f);
    v1 = v1 > 0.f ? v1 : (ex2f(v1 * LOG2E) - 1.f);
    *(__nv_bfloat162*)(outB + (size_t)row * FCAT + cp) = __floats2bfloat162_rn(v0, v1);
}

// ---------------- layer-2 reduce: sum JS2 partials + ELU + log_softmax ----
__global__ void reduce_lsm_kernel(const float* __restrict__ part,
                                  float* __restrict__ out) {
    int row = blockIdx.x * 8 + (threadIdx.x >> 5);
    int ln  = threadIdx.x & 31;
    float n0 = 0.f, n1 = 0.f, d = 0.f;
#pragma unroll
    for (int js = 0; js < JS2; ++js) {
        const float* b = part + ((size_t)js * GN + row) * 72;
        n0 += b[ln]; n1 += b[ln + 32]; d += b[64];
    }
    float inv = 1.f / d;
    float v0 = n0 * inv, v1 = n1 * inv;
    v0 = v0 > 0.f ? v0 : (__expf(v0) - 1.f);
    v1 = v1 > 0.f ? v1 : (__expf(v1) - 1.f);
    float mx = fmaxf(v0, v1);
#pragma unroll
    for (int o = 16; o; o >>= 1) mx = fmaxf(mx, __shfl_xor_sync(0xffffffffu, mx, o));
    float s = __expf(v0 - mx) + __expf(v1 - mx);
#pragma unroll
    for (int o = 16; o; o >>= 1) s += __shfl_xor_sync(0xffffffffu, s, o);
    float l = mx + __logf(s);
    out[(size_t)row * 64 + ln]      = v0 - l;
    out[(size_t)row * 64 + ln + 32] = v1 - l;
}

// ---------------- launch ----------------
extern "C" void kernel_launch(void* const* d_in, const int* in_sizes, int n_in,
                              void* d_out, int out_size) {
    const float* x   = (const float*)d_in[0];
    const int*   adj = (const int*)d_in[1];
    const float* W   = (const float*)d_in[2];
    const float* a1  = (const float*)d_in[3];
    const float* a2  = (const float*)d_in[4];
    const float* W2  = (const float*)d_in[5];
    const float* a21 = (const float*)d_in[6];
    const float* a22 = (const float*)d_in[7];
    float* out = (float*)d_out;

    uint32_t* adjbits; unsigned* gmaxi;
    float *s1, *e2, *e2b, *s21, *e22, *e22b, *part;
    __nv_bfloat16 *xb, *Wb, *W2b, *whTb, *hbufb, *whT2b;
    cudaGetSymbolAddress((void**)&adjbits, g_adjbits);
    cudaGetSymbolAddress((void**)&gmaxi, g_gmaxi);
    cudaGetSymbolAddress((void**)&xb,    g_xb);
    cudaGetSymbolAddress((void**)&Wb,    g_Wb);
    cudaGetSymbolAddress((void**)&W2b,   g_W2b);
    cudaGetSymbolAddress((void**)&whTb,  g_whTb);
    cudaGetSymbolAddress((void**)&s1,    g_s1);
    cudaGetSymbolAddress((void**)&e2,    g_e2);
    cudaGetSymbolAddress((void**)&e2b,   g_e2b);
    cudaGetSymbolAddress((void**)&hbufb, g_hbufb);
    cudaGetSymbolAddress((void**)&whT2b, g_whT2b);
    cudaGetSymbolAddress((void**)&s21,   g_s21);
    cudaGetSymbolAddress((void**)&e22,   g_e22);
    cudaGetSymbolAddress((void**)&e22b,  g_e22b);
    cudaGetSymbolAddress((void**)&part,  g_part);

    pack_adj_kernel<<<(GN * GN) / 1024, 256>>>(adj, adjbits, gmaxi);
    cvt_all_kernel<<<(GN * FCAT + FCAT * FCAT + HIDF * FCAT) / 512, 256>>>(
        x, xb, W, Wb, W2, W2b);
    gemm_bf16_nt<<<dim3(FCAT / 64, GN / 128), 256>>>(xb, Wb, whTb, FCAT,
                                                     a1, a2, s1, e2, e2b, gmaxi);
    attn_mma_kernel<JS1><<<dim3(GN / 128, GH, JS1), 128>>>(whTb, s1, e2, e2b,
                                                           gmaxi, adjbits, part);
    reduce_hbuf_kernel<<<GN, 256>>>(part, hbufb);
    gemm_bf16_nt<<<dim3(1, GN / 128), 256>>>(hbufb, W2b, whT2b, FCAT,
                                             a21, a22, s21, e22, e22b, gmaxi + 8);
    attn_mma_kernel<JS2><<<dim3(GN / 128, 1, JS2), 128>>>(whT2b, s21, e22, e22b,
                                                          gmaxi + 8, adjbits, part);
    reduce_lsm_kernel<<<GN / 8, 256>>>(part, out);
}